// round 4
// baseline (speedup 1.0000x reference)
#include <cuda_runtime.h>
#include <stdint.h>

#define NDU 60000
#define NDI 90000
#define NDOM (NDU + NDI)      /* 150000 */
#define NTU 200000
#define NTI 300000
#define NALL (NTU + NTI)      /* 500000 */
#define NE  2000000
#define DIM 32
#define NQ  8192
#define ALPHA 0.1f
#define BETA  0.9f
#define BSHIFT 13             /* 8192 nodes per bucket -> 1MB of rows */
#define NB 64                 /* 500000 >> 13 = 61 -> pad to 64 */

/* ---------------- static device scratch (no allocs allowed) ---------------- */
__device__ __align__(16) float g_X[(size_t)NALL * DIM];     /* 64 MB gather src */
__device__ __align__(16) float g_A[(size_t)NALL * DIM];     /* 64 MB accum h1 */
__device__ __align__(16) float g_light[(size_t)NDOM * DIM]; /* 19 MB */
__device__ __align__(16) float g_intra[(size_t)NDOM * DIM]; /* 19 MB */
__device__ float g_invs[4 * (size_t)NALL];  /* per-conv rsqrt(deg), 8 MB */
__device__ int   g_rs[4 * (size_t)NE];      /* binned edge records (SoA) */
__device__ int   g_rd[4 * (size_t)NE];
__device__ float g_rw[4 * (size_t)NE];
__device__ int   g_cnt[4 * NB];
__device__ int   g_cur[4 * NB];
__device__ int   g_remap[NALL];             /* node -> light row, or -1 */
__device__ int   g_f[2];                    /* index-width flags: 1 => int64 */

/* ---------------- edge-list addressing ---------------- */
__device__ __forceinline__ const int* src_ptr(int set, const int* dom, const int* sep) {
    return (set == 0) ? dom : sep + (size_t)(set - 1) * 2 * NE;
}
__device__ __forceinline__ const int* dst_ptr(int set, const int* dom, const int* sep) {
    return (set == 0) ? dom + NE : sep + (size_t)(set - 1) * 2 * NE + NE;
}

/* ---------------- prep kernels ---------------- */
__global__ void k_zero(float* p, size_t n) {
    size_t i = (size_t)blockIdx.x * blockDim.x + threadIdx.x;
    if (i < n) p[i] = 0.f;
}
__global__ void k_zero_cnt(int* cnt) {           /* 4*NB = 256 ints */
    cnt[threadIdx.x] = 0;
}
/* degree histogram + src-bucket histogram, all 4 convs in one pass */
__global__ void k_count(const int* __restrict__ dom, const int* __restrict__ sep,
                        float* __restrict__ invs, int* __restrict__ cnt) {
    size_t t = (size_t)blockIdx.x * blockDim.x + threadIdx.x;
    if (t >= (size_t)4 * NE) return;
    int set = (int)(t / NE);
    int e   = (int)(t - (size_t)set * NE);
    int s = __ldg(src_ptr(set, dom, sep) + e);
    int d = __ldg(dst_ptr(set, dom, sep) + e);
    atomicAdd(&invs[(size_t)set * NALL + d], 1.0f);
    atomicAdd(&cnt[set * NB + (s >> BSHIFT)], 1);
}
__global__ void k_rsqrt_all(float* d, size_t n) {
    size_t i = (size_t)blockIdx.x * blockDim.x + threadIdx.x;
    if (i < n) d[i] = rsqrtf(fmaxf(d[i], 1.0f));
}
/* exclusive prefix of bucket counts -> cursors (4 sets, trivial size) */
__global__ void k_prefix(const int* __restrict__ cnt, int* __restrict__ cur) {
    int set = threadIdx.x;
    if (set >= 4) return;
    int acc = 0;
    for (int b = 0; b < NB; b++) {
        cur[set * NB + b] = acc;
        acc += cnt[set * NB + b];
    }
}
/* reorder edges into src buckets, computing the folded edge weight on the fly */
__global__ void k_bin(const int* __restrict__ dom, const int* __restrict__ sep,
                      const float* __restrict__ invs, int* __restrict__ cur,
                      int* __restrict__ rs, int* __restrict__ rd, float* __restrict__ rw) {
    size_t t = (size_t)blockIdx.x * blockDim.x + threadIdx.x;
    if (t >= (size_t)4 * NE) return;
    int set = (int)(t / NE);
    int e   = (int)(t - (size_t)set * NE);
    int s = __ldg(src_ptr(set, dom, sep) + e);
    int d = __ldg(dst_ptr(set, dom, sep) + e);
    const float* iv = invs + (size_t)set * NALL;
    float w = BETA * __ldg(iv + s) * __ldg(iv + d);
    int pos = atomicAdd(&cur[set * NB + (s >> BSHIFT)], 1);
    size_t r = (size_t)set * NE + pos;
    rs[r] = s; rd[r] = d; rw[r] = w;
}

/* ---------------- remap ---------------- */
__global__ void k_remap_clear(int* m, int n) {
    int i = blockIdx.x * blockDim.x + threadIdx.x;
    if (i < n) m[i] = -1;
}
__global__ void k_remap_set(int* m, const int* __restrict__ uid, const int* __restrict__ iid) {
    int i = blockIdx.x * blockDim.x + threadIdx.x;
    if (i < NDU) m[uid[i]] = i;
    else if (i < NDOM) m[NTU + iid[i - NDU]] = i;
}

/* ---------------- inits ---------------- */
/* X = concat(a,b); A = ALPHA * X  (one pass, two outputs) */
__global__ void k_prepx(float4* __restrict__ X, float4* __restrict__ A,
                        const float4* __restrict__ a, const float4* __restrict__ b,
                        size_t na8, size_t n8) {
    size_t i = (size_t)blockIdx.x * blockDim.x + threadIdx.x;
    if (i >= n8) return;
    float4 v = (i < na8) ? a[i] : b[i - na8];
    X[i] = v;
    A[i] = make_float4(ALPHA * v.x, ALPHA * v.y, ALPHA * v.z, ALPHA * v.w);
}
/* d = ALPHA * s */
__global__ void k_init(float4* __restrict__ d, const float4* __restrict__ s, size_t n8) {
    size_t i = (size_t)blockIdx.x * blockDim.x + threadIdx.x;
    if (i >= n8) return;
    float4 v = s[i];
    d[i] = make_float4(ALPHA * v.x, ALPHA * v.y, ALPHA * v.z, ALPHA * v.w);
}
/* light[r] = 3*ALPHA * x[row(r)] gathered from aggru/aggri */
__global__ void k_light_init(float4* __restrict__ light, const float4* __restrict__ au,
                             const float4* __restrict__ ai, const int* __restrict__ uid,
                             const int* __restrict__ iid) {
    size_t i = (size_t)blockIdx.x * blockDim.x + threadIdx.x;
    if (i >= (size_t)NDOM * 8) return;
    int r = (int)(i >> 3);
    int c = (int)(i & 7);
    float4 v = (r < NDU) ? au[(size_t)uid[r] * 8 + c] : ai[(size_t)iid[r - NDU] * 8 + c];
    float k = 3.0f * ALPHA;
    light[i] = make_float4(k * v.x, k * v.y, k * v.z, k * v.w);
}

/* ---------------- scatter: 8 lanes/edge, f32 gather + f32 vector RED ------
   Edges pre-binned by src -> gather stream is cache-local.
   MODE 0: dense (dst row = dst).  MODE 2: remap into light, skip if <0.    */
template <int MODE>
__global__ void k_scatter(const int* __restrict__ rs, const int* __restrict__ rd,
                          const float* __restrict__ rw, const float* __restrict__ h,
                          float* __restrict__ agg, const int* __restrict__ remap, int nE) {
    size_t t = (size_t)blockIdx.x * blockDim.x + threadIdx.x;
    int e = (int)(t >> 3);
    int lane = (int)(t & 7);
    if (e >= nE) return;
    int d = __ldg(rd + e);
    int drow = d;
    if (MODE == 2) { drow = __ldg(remap + d); if (drow < 0) return; }
    int s = __ldg(rs + e);
    float ww = __ldg(rw + e);
    float4 v = *(const float4*)(h + (size_t)s * DIM + lane * 4);
    float* o = agg + (size_t)drow * DIM + lane * 4;
    asm volatile("red.global.add.v4.f32 [%0], {%1,%2,%3,%4};"
                 :: "l"(o), "f"(v.x * ww), "f"(v.y * ww),
                    "f"(v.z * ww), "f"(v.w * ww) : "memory");
}

/* ---------------- index width detect (both arrays, one launch) ---------- */
__global__ void k_detect2(const int* __restrict__ a, const int* __restrict__ b, int nElems) {
    __shared__ int any;
    const int* p = blockIdx.x ? b : a;
    if (threadIdx.x == 0) any = 0;
    __syncthreads();
    for (int i = threadIdx.x; i < nElems / 2; i += blockDim.x)
        if (p[2 * i + 1] != 0) any = 1;
    __syncthreads();
    if (threadIdx.x == 0) g_f[blockIdx.x] = (any == 0);
}

/* gamma[p] = dot(light_u, light_i)/9 + dot(intra_u, intra_i); one warp/pair */
__global__ void k_gamma(const void* __restrict__ users, const void* __restrict__ items,
                        const float* __restrict__ light, const float* __restrict__ intra,
                        float* __restrict__ out) {
    int p = (blockIdx.x * blockDim.x + threadIdx.x) >> 5;
    int lane = threadIdx.x & 31;
    if (p >= NQ) return;
    long long u  = g_f[0] ? ((const long long*)users)[p] : (long long)((const int*)users)[p];
    long long it = g_f[1] ? ((const long long*)items)[p] : (long long)((const int*)items)[p];
    size_t ur = (size_t)u * DIM + lane;
    size_t ir = ((size_t)NDU + (size_t)it) * DIM + lane;
    float v = light[ur] * light[ir] * (1.0f / 9.0f) + intra[ur] * intra[ir];
#pragma unroll
    for (int o = 16; o; o >>= 1) v += __shfl_xor_sync(0xffffffffu, v, o);
    if (lane == 0) out[p] = v;
}

/* ---------------- host side ---------------- */
static inline unsigned gb(size_t n) { return (unsigned)((n + 255) / 256); }

extern "C" void kernel_launch(void* const* d_in, const int* in_sizes, int n_in,
                              void* d_out, int out_size) {
    const int*   dom   = (const int*)d_in[0];    /* [2, NE] */
    const int*   sep   = (const int*)d_in[1];    /* [3, 2, NE] */
    const float* aggru = (const float*)d_in[2];  /* [NTU, DIM] */
    const float* aggri = (const float*)d_in[3];  /* [NTI, DIM] */
    const float* domu  = (const float*)d_in[4];  /* [NDU, DIM] */
    const float* domi  = (const float*)d_in[5];  /* [NDI, DIM] */
    const int*   uid   = (const int*)d_in[6];    /* [NDU] */
    const int*   iid   = (const int*)d_in[7];    /* [NDI] */
    const void*  users = d_in[8];                /* [NQ] int32 or int64 */
    const void*  items = d_in[9];
    float* out = (float*)d_out;

    float *X, *A, *light, *intra, *invs, *rw;
    int *rs, *rd, *cnt, *cur, *remap;
    cudaGetSymbolAddress((void**)&X, g_X);
    cudaGetSymbolAddress((void**)&A, g_A);
    cudaGetSymbolAddress((void**)&light, g_light);
    cudaGetSymbolAddress((void**)&intra, g_intra);
    cudaGetSymbolAddress((void**)&invs, g_invs);
    cudaGetSymbolAddress((void**)&rs, g_rs);
    cudaGetSymbolAddress((void**)&rd, g_rd);
    cudaGetSymbolAddress((void**)&rw, g_rw);
    cudaGetSymbolAddress((void**)&cnt, g_cnt);
    cudaGetSymbolAddress((void**)&cur, g_cur);
    cudaGetSymbolAddress((void**)&remap, g_remap);

    const size_t nd8  = (size_t)NDOM * 8;
    const size_t na8  = (size_t)NALL * 8;
    const size_t nu8  = (size_t)NDU * 8;
    const size_t ntu8 = (size_t)NTU * 8;

    /* --- one-time prep: detect, remap, degrees, edge binning (all 4 convs) --- */
    k_detect2<<<2, 256>>>((const int*)users, (const int*)items, NQ);
    k_remap_clear<<<gb(NALL), 256>>>(remap, NALL);
    k_remap_set<<<gb(NDOM), 256>>>(remap, uid, iid);
    k_zero<<<gb((size_t)4 * NALL), 256>>>(invs, (size_t)4 * NALL);
    k_zero_cnt<<<1, 4 * NB>>>(cnt);
    k_count<<<gb((size_t)4 * NE), 256>>>(dom, sep, invs, cnt);
    k_rsqrt_all<<<gb((size_t)4 * NALL), 256>>>(invs, (size_t)4 * NALL);
    k_prefix<<<1, 32>>>(cnt, cur);
    k_bin<<<gb((size_t)4 * NE), 256>>>(dom, sep, invs, cur, rs, rd, rw);

    /* --- intra-domain conv (150K nodes), set 0 --- */
    k_prepx<<<gb(nd8), 256>>>((float4*)X, (float4*)A,
                              (const float4*)domu, (const float4*)domi, nu8, nd8);
    k_scatter<0><<<gb((size_t)NE * 8), 256>>>(rs, rd, rw, X, A, 0, NE);
    k_init<<<gb(nd8), 256>>>((float4*)intra, (const float4*)X, nd8);
    k_scatter<0><<<gb((size_t)NE * 8), 256>>>(rs, rd, rw, A, intra, 0, NE);

    /* --- inter-domain: 3 convs (sets 1..3); layer-2 REDs straight into light --- */
    k_prepx<<<gb(na8), 256>>>((float4*)X, (float4*)A,
                              (const float4*)aggru, (const float4*)aggri, ntu8, na8);
    k_light_init<<<gb(nd8), 256>>>((float4*)light, (const float4*)aggru,
                                   (const float4*)aggri, uid, iid);
    for (int d = 0; d < 3; d++) {
        const int*   rsd = rs + (size_t)(d + 1) * NE;
        const int*   rdd = rd + (size_t)(d + 1) * NE;
        const float* rwd = rw + (size_t)(d + 1) * NE;
        if (d > 0) k_init<<<gb(na8), 256>>>((float4*)A, (const float4*)X, na8);
        k_scatter<0><<<gb((size_t)NE * 8), 256>>>(rsd, rdd, rwd, X, A, 0, NE);
        k_scatter<2><<<gb((size_t)NE * 8), 256>>>(rsd, rdd, rwd, A, light, remap, NE);
    }

    /* --- final pairwise dots --- */
    k_gamma<<<NQ / 8, 256>>>(users, items, light, intra, out);
}

// round 5
// speedup vs baseline: 3.5485x; 3.5485x over previous
#include <cuda_runtime.h>
#include <stdint.h>

#define NDU 60000
#define NDI 90000
#define NDOM (NDU + NDI)      /* 150000 */
#define NTU 200000
#define NTI 300000
#define NALL (NTU + NTI)      /* 500000 */
#define NE  2000000
#define DIM 32
#define NQ  8192
#define ALPHA 0.1f
#define BETA  0.9f
#define BSHIFT 13             /* 8192 nodes per bucket -> 1MB of feature rows */
#define NB 64                 /* 500000 >> 13 = 61 -> pad to 64 */
#define CPAD 256              /* counter stride in ints (1KB) -> distinct L2 slices */

/* ---------------- static device scratch (no allocs allowed) ---------------- */
__device__ __align__(16) float g_X[(size_t)NALL * DIM];     /* 64 MB gather src */
__device__ __align__(16) float g_A[(size_t)NALL * DIM];     /* 64 MB accum h1 */
__device__ __align__(16) float g_light[(size_t)NDOM * DIM]; /* 19 MB */
__device__ __align__(16) float g_intra[(size_t)NDOM * DIM]; /* 19 MB */
__device__ float g_invs[4 * (size_t)NALL];  /* per-conv rsqrt(deg), 8 MB */
__device__ int   g_rs[4 * (size_t)NE];      /* binned edge records (SoA) */
__device__ int   g_rd[4 * (size_t)NE];
__device__ float g_rw[4 * (size_t)NE];
__device__ int   g_cnt[4 * NB * CPAD];      /* padded: 1 counter per 1KB */
__device__ int   g_cur[4 * NB * CPAD];
__device__ int   g_remap[NALL];             /* node -> light row, or -1 */
__device__ int   g_f[2];                    /* index-width flags: 1 => int64 */

__device__ __forceinline__ int ctr(int set, int b) { return (set * NB + b) * CPAD; }

/* ---------------- edge-list addressing ---------------- */
__device__ __forceinline__ const int* src_ptr(int set, const int* dom, const int* sep) {
    return (set == 0) ? dom : sep + (size_t)(set - 1) * 2 * NE;
}
__device__ __forceinline__ const int* dst_ptr(int set, const int* dom, const int* sep) {
    return (set == 0) ? dom + NE : sep + (size_t)(set - 1) * 2 * NE + NE;
}

/* ---------------- prep kernels ---------------- */
__global__ void k_zero(float* p, size_t n) {
    size_t i = (size_t)blockIdx.x * blockDim.x + threadIdx.x;
    if (i < n) p[i] = 0.f;
}
__global__ void k_zero_i(int* p, size_t n) {
    size_t i = (size_t)blockIdx.x * blockDim.x + threadIdx.x;
    if (i < n) p[i] = 0;
}
/* degree histogram + src-bucket histogram (padded counters), all 4 convs */
__global__ void k_count(const int* __restrict__ dom, const int* __restrict__ sep,
                        float* __restrict__ invs, int* __restrict__ cnt) {
    size_t t = (size_t)blockIdx.x * blockDim.x + threadIdx.x;
    if (t >= (size_t)4 * NE) return;
    int set = (int)(t / NE);
    int e   = (int)(t - (size_t)set * NE);
    int s = __ldg(src_ptr(set, dom, sep) + e);
    int d = __ldg(dst_ptr(set, dom, sep) + e);
    atomicAdd(&invs[(size_t)set * NALL + d], 1.0f);
    atomicAdd(&cnt[ctr(set, s >> BSHIFT)], 1);
}
__global__ void k_rsqrt_all(float* d, size_t n) {
    size_t i = (size_t)blockIdx.x * blockDim.x + threadIdx.x;
    if (i < n) d[i] = rsqrtf(fmaxf(d[i], 1.0f));
}
/* exclusive prefix of bucket counts -> cursors (4 sets, trivial size) */
__global__ void k_prefix(const int* __restrict__ cnt, int* __restrict__ cur) {
    int set = threadIdx.x;
    if (set >= 4) return;
    int acc = 0;
    for (int b = 0; b < NB; b++) {
        cur[ctr(set, b)] = acc;
        acc += cnt[ctr(set, b)];
    }
}
/* reorder edges into src buckets, computing the folded edge weight on the fly */
__global__ void k_bin(const int* __restrict__ dom, const int* __restrict__ sep,
                      const float* __restrict__ invs, int* __restrict__ cur,
                      int* __restrict__ rs, int* __restrict__ rd, float* __restrict__ rw) {
    size_t t = (size_t)blockIdx.x * blockDim.x + threadIdx.x;
    if (t >= (size_t)4 * NE) return;
    int set = (int)(t / NE);
    int e   = (int)(t - (size_t)set * NE);
    int s = __ldg(src_ptr(set, dom, sep) + e);
    int d = __ldg(dst_ptr(set, dom, sep) + e);
    const float* iv = invs + (size_t)set * NALL;
    float w = BETA * __ldg(iv + s) * __ldg(iv + d);
    int pos = atomicAdd(&cur[ctr(set, s >> BSHIFT)], 1);
    size_t r = (size_t)set * NE + pos;
    rs[r] = s; rd[r] = d; rw[r] = w;
}

/* ---------------- remap ---------------- */
__global__ void k_remap_clear(int* m, int n) {
    int i = blockIdx.x * blockDim.x + threadIdx.x;
    if (i < n) m[i] = -1;
}
__global__ void k_remap_set(int* m, const int* __restrict__ uid, const int* __restrict__ iid) {
    int i = blockIdx.x * blockDim.x + threadIdx.x;
    if (i < NDU) m[uid[i]] = i;
    else if (i < NDOM) m[NTU + iid[i - NDU]] = i;
}

/* ---------------- inits ---------------- */
/* X = concat(a,b); A = ALPHA * X  (one pass, two outputs) */
__global__ void k_prepx(float4* __restrict__ X, float4* __restrict__ A,
                        const float4* __restrict__ a, const float4* __restrict__ b,
                        size_t na8, size_t n8) {
    size_t i = (size_t)blockIdx.x * blockDim.x + threadIdx.x;
    if (i >= n8) return;
    float4 v = (i < na8) ? a[i] : b[i - na8];
    X[i] = v;
    A[i] = make_float4(ALPHA * v.x, ALPHA * v.y, ALPHA * v.z, ALPHA * v.w);
}
/* d = ALPHA * s */
__global__ void k_init(float4* __restrict__ d, const float4* __restrict__ s, size_t n8) {
    size_t i = (size_t)blockIdx.x * blockDim.x + threadIdx.x;
    if (i >= n8) return;
    float4 v = s[i];
    d[i] = make_float4(ALPHA * v.x, ALPHA * v.y, ALPHA * v.z, ALPHA * v.w);
}
/* light[r] = 3*ALPHA * x[row(r)] gathered from aggru/aggri */
__global__ void k_light_init(float4* __restrict__ light, const float4* __restrict__ au,
                             const float4* __restrict__ ai, const int* __restrict__ uid,
                             const int* __restrict__ iid) {
    size_t i = (size_t)blockIdx.x * blockDim.x + threadIdx.x;
    if (i >= (size_t)NDOM * 8) return;
    int r = (int)(i >> 3);
    int c = (int)(i & 7);
    float4 v = (r < NDU) ? au[(size_t)uid[r] * 8 + c] : ai[(size_t)iid[r - NDU] * 8 + c];
    float k = 3.0f * ALPHA;
    light[i] = make_float4(k * v.x, k * v.y, k * v.z, k * v.w);
}

/* ---------------- scatter: 8 lanes/edge, f32 gather + f32 vector RED ------
   Edges pre-binned by src -> gather stream is cache-local.
   MODE 0: dense (dst row = dst).  MODE 2: remap into light, skip if <0.    */
template <int MODE>
__global__ void k_scatter(const int* __restrict__ rs, const int* __restrict__ rd,
                          const float* __restrict__ rw, const float* __restrict__ h,
                          float* __restrict__ agg, const int* __restrict__ remap, int nE) {
    size_t t = (size_t)blockIdx.x * blockDim.x + threadIdx.x;
    int e = (int)(t >> 3);
    int lane = (int)(t & 7);
    if (e >= nE) return;
    int d = __ldg(rd + e);
    int drow = d;
    if (MODE == 2) { drow = __ldg(remap + d); if (drow < 0) return; }
    int s = __ldg(rs + e);
    float ww = __ldg(rw + e);
    float4 v = *(const float4*)(h + (size_t)s * DIM + lane * 4);
    float* o = agg + (size_t)drow * DIM + lane * 4;
    asm volatile("red.global.add.v4.f32 [%0], {%1,%2,%3,%4};"
                 :: "l"(o), "f"(v.x * ww), "f"(v.y * ww),
                    "f"(v.z * ww), "f"(v.w * ww) : "memory");
}

/* ---------------- index width detect (both arrays, one launch) ---------- */
__global__ void k_detect2(const int* __restrict__ a, const int* __restrict__ b, int nElems) {
    __shared__ int any;
    const int* p = blockIdx.x ? b : a;
    if (threadIdx.x == 0) any = 0;
    __syncthreads();
    for (int i = threadIdx.x; i < nElems / 2; i += blockDim.x)
        if (p[2 * i + 1] != 0) any = 1;
    __syncthreads();
    if (threadIdx.x == 0) g_f[blockIdx.x] = (any == 0);
}

/* gamma[p] = dot(light_u, light_i)/9 + dot(intra_u, intra_i); one warp/pair */
__global__ void k_gamma(const void* __restrict__ users, const void* __restrict__ items,
                        const float* __restrict__ light, const float* __restrict__ intra,
                        float* __restrict__ out) {
    int p = (blockIdx.x * blockDim.x + threadIdx.x) >> 5;
    int lane = threadIdx.x & 31;
    if (p >= NQ) return;
    long long u  = g_f[0] ? ((const long long*)users)[p] : (long long)((const int*)users)[p];
    long long it = g_f[1] ? ((const long long*)items)[p] : (long long)((const int*)items)[p];
    size_t ur = (size_t)u * DIM + lane;
    size_t ir = ((size_t)NDU + (size_t)it) * DIM + lane;
    float v = light[ur] * light[ir] * (1.0f / 9.0f) + intra[ur] * intra[ir];
#pragma unroll
    for (int o = 16; o; o >>= 1) v += __shfl_xor_sync(0xffffffffu, v, o);
    if (lane == 0) out[p] = v;
}

/* ---------------- host side ---------------- */
static inline unsigned gb(size_t n) { return (unsigned)((n + 255) / 256); }

extern "C" void kernel_launch(void* const* d_in, const int* in_sizes, int n_in,
                              void* d_out, int out_size) {
    const int*   dom   = (const int*)d_in[0];    /* [2, NE] */
    const int*   sep   = (const int*)d_in[1];    /* [3, 2, NE] */
    const float* aggru = (const float*)d_in[2];  /* [NTU, DIM] */
    const float* aggri = (const float*)d_in[3];  /* [NTI, DIM] */
    const float* domu  = (const float*)d_in[4];  /* [NDU, DIM] */
    const float* domi  = (const float*)d_in[5];  /* [NDI, DIM] */
    const int*   uid   = (const int*)d_in[6];    /* [NDU] */
    const int*   iid   = (const int*)d_in[7];    /* [NDI] */
    const void*  users = d_in[8];                /* [NQ] int32 or int64 */
    const void*  items = d_in[9];
    float* out = (float*)d_out;

    float *X, *A, *light, *intra, *invs, *rw;
    int *rs, *rd, *cnt, *cur, *remap;
    cudaGetSymbolAddress((void**)&X, g_X);
    cudaGetSymbolAddress((void**)&A, g_A);
    cudaGetSymbolAddress((void**)&light, g_light);
    cudaGetSymbolAddress((void**)&intra, g_intra);
    cudaGetSymbolAddress((void**)&invs, g_invs);
    cudaGetSymbolAddress((void**)&rs, g_rs);
    cudaGetSymbolAddress((void**)&rd, g_rd);
    cudaGetSymbolAddress((void**)&rw, g_rw);
    cudaGetSymbolAddress((void**)&cnt, g_cnt);
    cudaGetSymbolAddress((void**)&cur, g_cur);
    cudaGetSymbolAddress((void**)&remap, g_remap);

    const size_t nd8  = (size_t)NDOM * 8;
    const size_t na8  = (size_t)NALL * 8;
    const size_t nu8  = (size_t)NDU * 8;
    const size_t ntu8 = (size_t)NTU * 8;

    /* --- one-time prep: detect, remap, degrees, edge binning (all 4 convs) --- */
    k_detect2<<<2, 256>>>((const int*)users, (const int*)items, NQ);
    k_remap_clear<<<gb(NALL), 256>>>(remap, NALL);
    k_remap_set<<<gb(NDOM), 256>>>(remap, uid, iid);
    k_zero<<<gb((size_t)4 * NALL), 256>>>(invs, (size_t)4 * NALL);
    k_zero_i<<<gb((size_t)4 * NB * CPAD), 256>>>(cnt, (size_t)4 * NB * CPAD);
    k_count<<<gb((size_t)4 * NE), 256>>>(dom, sep, invs, cnt);
    k_rsqrt_all<<<gb((size_t)4 * NALL), 256>>>(invs, (size_t)4 * NALL);
    k_prefix<<<1, 32>>>(cnt, cur);
    k_bin<<<gb((size_t)4 * NE), 256>>>(dom, sep, invs, cur, rs, rd, rw);

    /* --- intra-domain conv (150K nodes), set 0 --- */
    k_prepx<<<gb(nd8), 256>>>((float4*)X, (float4*)A,
                              (const float4*)domu, (const float4*)domi, nu8, nd8);
    k_scatter<0><<<gb((size_t)NE * 8), 256>>>(rs, rd, rw, X, A, 0, NE);
    k_init<<<gb(nd8), 256>>>((float4*)intra, (const float4*)X, nd8);
    k_scatter<0><<<gb((size_t)NE * 8), 256>>>(rs, rd, rw, A, intra, 0, NE);

    /* --- inter-domain: 3 convs (sets 1..3); layer-2 REDs straight into light --- */
    k_prepx<<<gb(na8), 256>>>((float4*)X, (float4*)A,
                              (const float4*)aggru, (const float4*)aggri, ntu8, na8);
    k_light_init<<<gb(nd8), 256>>>((float4*)light, (const float4*)aggru,
                                   (const float4*)aggri, uid, iid);
    for (int d = 0; d < 3; d++) {
        const int*   rsd = rs + (size_t)(d + 1) * NE;
        const int*   rdd = rd + (size_t)(d + 1) * NE;
        const float* rwd = rw + (size_t)(d + 1) * NE;
        if (d > 0) k_init<<<gb(na8), 256>>>((float4*)A, (const float4*)X, na8);
        k_scatter<0><<<gb((size_t)NE * 8), 256>>>(rsd, rdd, rwd, X, A, 0, NE);
        k_scatter<2><<<gb((size_t)NE * 8), 256>>>(rsd, rdd, rwd, A, light, remap, NE);
    }

    /* --- final pairwise dots --- */
    k_gamma<<<NQ / 8, 256>>>(users, items, light, intra, out);
}

// round 6
// speedup vs baseline: 5.8354x; 1.6445x over previous
#include <cuda_runtime.h>
#include <stdint.h>

#define NDU 60000
#define NDI 90000
#define NDOM (NDU + NDI)      /* 150000 */
#define NTU 200000
#define NTI 300000
#define NALL (NTU + NTI)      /* 500000 */
#define NE  2000000
#define DIM 32
#define NQ  8192
#define ALPHA 0.1f
#define BETA  0.9f
#define CPAD 256              /* counter stride in ints (1KB) -> distinct L2 slices */
/* counters: k*CPAD.  k = set (L2 list), 4+set (L1 list), 8+set (init list) */

/* ---------------- static device scratch (no allocs allowed) ---------------- */
__device__ __align__(16) float g_A[(size_t)NALL * DIM];     /* 64 MB accum h1 */
__device__ __align__(16) float g_light[(size_t)NDOM * DIM]; /* 19 MB */
__device__ __align__(16) float g_intra[(size_t)NDOM * DIM]; /* 19 MB */
__device__ float   g_invs[4 * (size_t)NALL];   /* per-conv rsqrt(deg) */
__device__ int     g_l2s[4 * (size_t)NE];      /* compacted layer-2 edges */
__device__ int     g_l2d[4 * (size_t)NE];      /* (dst already remapped) */
__device__ float   g_l2w[4 * (size_t)NE];
__device__ int     g_l1s[4 * (size_t)NE];      /* compacted layer-1 edges */
__device__ int     g_l1d[4 * (size_t)NE];
__device__ float   g_l1w[4 * (size_t)NE];
__device__ int     g_ini[4 * (size_t)NALL];    /* nodes needing A init, per set */
__device__ int     g_needA[4 * (size_t)NALL];  /* layer-1 output needed? */
__device__ int     g_remap[NALL];              /* global node -> light row, or -1 */
__device__ uint8_t g_needL[NDOM];              /* dom row needed by gamma? */
__device__ int     g_cnt[12 * CPAD];
__device__ int     g_f[2];                     /* index-width flags: 1 => int64 */

/* ---------------- edge-list addressing ---------------- */
__device__ __forceinline__ const int* src_ptr(int set, const int* dom, const int* sep) {
    return (set == 0) ? dom : sep + (size_t)(set - 1) * 2 * NE;
}
__device__ __forceinline__ const int* dst_ptr(int set, const int* dom, const int* sep) {
    return (set == 0) ? dom + NE : sep + (size_t)(set - 1) * 2 * NE + NE;
}

/* warp-aggregated append: one atomic per warp per counter (set uniform in warp) */
__device__ __forceinline__ int wagg_append(int* ctr, bool pred) {
    unsigned m = __ballot_sync(0xffffffffu, pred);
    if (!m) return -1;
    int lane = threadIdx.x & 31;
    int leader = __ffs(m) - 1;
    int base = 0;
    if (lane == leader) base = atomicAdd(ctr, __popc(m));
    base = __shfl_sync(0xffffffffu, base, leader);
    return pred ? base + __popc(m & ((1u << lane) - 1u)) : -1;
}

/* ---------------- tiny setup kernels ---------------- */
__global__ void k_preset(int* cnt) {            /* counters + flags */
    for (int i = threadIdx.x; i < 12 * CPAD; i += blockDim.x) cnt[i] = 0;
    if (threadIdx.x < 2) g_f[threadIdx.x] = 1;
}
__global__ void k_detect(const int* __restrict__ a, const int* __restrict__ b) {
    int arr = blockIdx.x >> 5;                   /* 64 blocks: 32 per array */
    const int* p = arr ? b : a;
    int i = (blockIdx.x & 31) * 256 + threadIdx.x;   /* odd-word index */
    if (i < NQ && p[2 * i + 1] != 0) g_f[arr] = 0;   /* benign race */
}
__global__ void k_zero_i(int* p, size_t n) {
    size_t i = (size_t)blockIdx.x * blockDim.x + threadIdx.x;
    if (i < n) p[i] = 0;
}
__global__ void k_zero_f(float* p, size_t n) {
    size_t i = (size_t)blockIdx.x * blockDim.x + threadIdx.x;
    if (i < n) p[i] = 0.f;
}
__global__ void k_zero_b(uint8_t* p, size_t n) {
    size_t i = (size_t)blockIdx.x * blockDim.x + threadIdx.x;
    if (i < n) p[i] = 0;
}
__global__ void k_fill_m1(int* p, size_t n) {
    size_t i = (size_t)blockIdx.x * blockDim.x + threadIdx.x;
    if (i < n) p[i] = -1;
}
/* mark dom rows referenced by users/items */
__global__ void k_needL(uint8_t* __restrict__ needL, const void* __restrict__ users,
                        const void* __restrict__ items) {
    int i = blockIdx.x * blockDim.x + threadIdx.x;
    if (i >= NQ) return;
    long long u  = g_f[0] ? ((const long long*)users)[i] : (long long)((const int*)users)[i];
    long long it = g_f[1] ? ((const long long*)items)[i] : (long long)((const int*)items)[i];
    needL[u] = 1;
    needL[NDU + it] = 1;
}
/* global node -> light row, only for needed rows */
__global__ void k_remapG(int* __restrict__ remap, const uint8_t* __restrict__ needL,
                         const int* __restrict__ uid, const int* __restrict__ iid) {
    int r = blockIdx.x * blockDim.x + threadIdx.x;
    if (r >= NDOM || !needL[r]) return;
    int node = (r < NDU) ? uid[r] : NTU + iid[r - NDU];
    remap[node] = r;
}

/* ---------------- degrees ---------------- */
__global__ void k_deg_all(const int* __restrict__ dom, const int* __restrict__ sep,
                          float* __restrict__ invs) {
    size_t t = (size_t)blockIdx.x * blockDim.x + threadIdx.x;
    if (t >= (size_t)4 * NE) return;
    int set = (int)(t / NE);
    int e   = (int)(t - (size_t)set * NE);
    atomicAdd(&invs[(size_t)set * NALL + __ldg(dst_ptr(set, dom, sep) + e)], 1.0f);
}
__global__ void k_rsqrt_all(float* d, size_t n) {
    size_t i = (size_t)blockIdx.x * blockDim.x + threadIdx.x;
    if (i < n) d[i] = rsqrtf(fmaxf(d[i], 1.0f));
}

/* ---------------- pass A: compact layer-2 edges, mark+list needA -------- */
__global__ void k_passA(const int* __restrict__ dom, const int* __restrict__ sep,
                        const float* __restrict__ invs, const uint8_t* __restrict__ needL,
                        const int* __restrict__ remap, int* __restrict__ needA,
                        int* __restrict__ cnt, int* __restrict__ l2s, int* __restrict__ l2d,
                        float* __restrict__ l2w, int* __restrict__ ini) {
    size_t t = (size_t)blockIdx.x * blockDim.x + threadIdx.x;
    bool in = t < (size_t)4 * NE;
    int set = in ? (int)(t / NE) : 3;            /* set uniform per warp (NE%32==0) */
    int e   = in ? (int)(t - (size_t)set * NE) : 0;
    int s = 0, d = 0, drow = -1;
    bool valid = false;
    if (in) {
        s = __ldg(src_ptr(set, dom, sep) + e);
        d = __ldg(dst_ptr(set, dom, sep) + e);
        if (set == 0) { valid = (__ldg(needL + d) != 0); drow = d; }
        else          { drow = __ldg(remap + d); valid = (drow >= 0); }
    }
    int pos = wagg_append(&cnt[set * CPAD], valid);
    if (valid) {
        const float* iv = invs + (size_t)set * NALL;
        size_t o = (size_t)set * NE + pos;
        l2s[o] = s; l2d[o] = drow;
        l2w[o] = BETA * __ldg(iv + s) * __ldg(iv + d);
    }
    bool fresh = valid && (atomicExch(&needA[(size_t)set * NALL + s], 1) == 0);
    int ipos = wagg_append(&cnt[(8 + set) * CPAD], fresh);
    if (fresh) ini[(size_t)set * NALL + ipos] = s;
}

/* ---------------- pass B: compact layer-1 edges -------- */
__global__ void k_passB(const int* __restrict__ dom, const int* __restrict__ sep,
                        const float* __restrict__ invs, const int* __restrict__ needA,
                        int* __restrict__ cnt, int* __restrict__ l1s, int* __restrict__ l1d,
                        float* __restrict__ l1w) {
    size_t t = (size_t)blockIdx.x * blockDim.x + threadIdx.x;
    bool in = t < (size_t)4 * NE;
    int set = in ? (int)(t / NE) : 3;
    int e   = in ? (int)(t - (size_t)set * NE) : 0;
    int s = 0, d = 0;
    bool valid = false;
    if (in) {
        s = __ldg(src_ptr(set, dom, sep) + e);
        d = __ldg(dst_ptr(set, dom, sep) + e);
        valid = (__ldg(needA + (size_t)set * NALL + d) != 0);
    }
    int pos = wagg_append(&cnt[(4 + set) * CPAD], valid);
    if (valid) {
        const float* iv = invs + (size_t)set * NALL;
        size_t o = (size_t)set * NE + pos;
        l1s[o] = s; l1d[o] = d;
        l1w[o] = BETA * __ldg(iv + s) * __ldg(iv + d);
    }
}

/* ---------------- split gather from the two input tables ---------------- */
__device__ __forceinline__ float4 gatherX(const float* __restrict__ xu,
                                          const float* __restrict__ xi,
                                          int splitU, int node, int lane) {
    const float* p = (node < splitU) ? xu + (size_t)node * DIM
                                     : xi + (size_t)(node - splitU) * DIM;
    return *(const float4*)(p + lane * 4);
}

/* ---------------- inits ---------------- */
/* A[node] = ALPHA * x[node] at listed nodes only; 8 lanes/node */
__global__ void k_initA(const int* __restrict__ list, const int* __restrict__ cnt,
                        const float* __restrict__ xu, const float* __restrict__ xi,
                        int splitU, float* __restrict__ A) {
    size_t t = (size_t)blockIdx.x * blockDim.x + threadIdx.x;
    int r = (int)(t >> 3), lane = (int)(t & 7);
    if (r >= __ldg(cnt)) return;
    int node = __ldg(list + r);
    float4 v = gatherX(xu, xi, splitU, node, lane);
    *(float4*)(A + (size_t)node * DIM + lane * 4) =
        make_float4(ALPHA * v.x, ALPHA * v.y, ALPHA * v.z, ALPHA * v.w);
}
/* d = ALPHA * concat(a,b) over all dom rows (intra accumulator) */
__global__ void k_init_split(float4* __restrict__ d, const float4* __restrict__ a,
                             const float4* __restrict__ b, size_t na8, size_t n8) {
    size_t i = (size_t)blockIdx.x * blockDim.x + threadIdx.x;
    if (i >= n8) return;
    float4 v = (i < na8) ? a[i] : b[i - na8];
    d[i] = make_float4(ALPHA * v.x, ALPHA * v.y, ALPHA * v.z, ALPHA * v.w);
}
/* light[r] = 3*ALPHA * x_global[row(r)] */
__global__ void k_light_init(float4* __restrict__ light, const float4* __restrict__ au,
                             const float4* __restrict__ ai, const int* __restrict__ uid,
                             const int* __restrict__ iid) {
    size_t i = (size_t)blockIdx.x * blockDim.x + threadIdx.x;
    if (i >= (size_t)NDOM * 8) return;
    int r = (int)(i >> 3);
    int c = (int)(i & 7);
    float4 v = (r < NDU) ? au[(size_t)uid[r] * 8 + c] : ai[(size_t)iid[r - NDU] * 8 + c];
    float k = 3.0f * ALPHA;
    light[i] = make_float4(k * v.x, k * v.y, k * v.z, k * v.w);
}

/* ---------------- scatters over compacted lists, 8 lanes/edge ------------ */
/* layer-1: gather split input tables -> RED into A */
__global__ void k_scatL1(const int* __restrict__ es, const int* __restrict__ ed,
                         const float* __restrict__ ew, const int* __restrict__ cnt,
                         const float* __restrict__ xu, const float* __restrict__ xi,
                         int splitU, float* __restrict__ A) {
    size_t t = (size_t)blockIdx.x * blockDim.x + threadIdx.x;
    int e = (int)(t >> 3), lane = (int)(t & 7);
    if (e >= __ldg(cnt)) return;
    int s = __ldg(es + e), d = __ldg(ed + e);
    float w = __ldg(ew + e);
    float4 v = gatherX(xu, xi, splitU, s, lane);
    float* o = A + (size_t)d * DIM + lane * 4;
    asm volatile("red.global.add.v4.f32 [%0], {%1,%2,%3,%4};"
                 :: "l"(o), "f"(v.x * w), "f"(v.y * w),
                    "f"(v.z * w), "f"(v.w * w) : "memory");
}
/* layer-2: gather A -> RED into target (dst pre-remapped) */
__global__ void k_scatL2(const int* __restrict__ es, const int* __restrict__ ed,
                         const float* __restrict__ ew, const int* __restrict__ cnt,
                         const float* __restrict__ A, float* __restrict__ tgt) {
    size_t t = (size_t)blockIdx.x * blockDim.x + threadIdx.x;
    int e = (int)(t >> 3), lane = (int)(t & 7);
    if (e >= __ldg(cnt)) return;
    int s = __ldg(es + e), d = __ldg(ed + e);
    float w = __ldg(ew + e);
    float4 v = *(const float4*)(A + (size_t)s * DIM + lane * 4);
    float* o = tgt + (size_t)d * DIM + lane * 4;
    asm volatile("red.global.add.v4.f32 [%0], {%1,%2,%3,%4};"
                 :: "l"(o), "f"(v.x * w), "f"(v.y * w),
                    "f"(v.z * w), "f"(v.w * w) : "memory");
}

/* gamma[p] = dot(light_u, light_i)/9 + dot(intra_u, intra_i); one warp/pair */
__global__ void k_gamma(const void* __restrict__ users, const void* __restrict__ items,
                        const float* __restrict__ light, const float* __restrict__ intra,
                        float* __restrict__ out) {
    int p = (blockIdx.x * blockDim.x + threadIdx.x) >> 5;
    int lane = threadIdx.x & 31;
    if (p >= NQ) return;
    long long u  = g_f[0] ? ((const long long*)users)[p] : (long long)((const int*)users)[p];
    long long it = g_f[1] ? ((const long long*)items)[p] : (long long)((const int*)items)[p];
    size_t ur = (size_t)u * DIM + lane;
    size_t ir = ((size_t)NDU + (size_t)it) * DIM + lane;
    float v = light[ur] * light[ir] * (1.0f / 9.0f) + intra[ur] * intra[ir];
#pragma unroll
    for (int o = 16; o; o >>= 1) v += __shfl_xor_sync(0xffffffffu, v, o);
    if (lane == 0) out[p] = v;
}

/* ---------------- host side ---------------- */
static inline unsigned gb(size_t n) { return (unsigned)((n + 255) / 256); }

extern "C" void kernel_launch(void* const* d_in, const int* in_sizes, int n_in,
                              void* d_out, int out_size) {
    const int*   dom   = (const int*)d_in[0];    /* [2, NE] */
    const int*   sep   = (const int*)d_in[1];    /* [3, 2, NE] */
    const float* aggru = (const float*)d_in[2];  /* [NTU, DIM] */
    const float* aggri = (const float*)d_in[3];  /* [NTI, DIM] */
    const float* domu  = (const float*)d_in[4];  /* [NDU, DIM] */
    const float* domi  = (const float*)d_in[5];  /* [NDI, DIM] */
    const int*   uid   = (const int*)d_in[6];    /* [NDU] */
    const int*   iid   = (const int*)d_in[7];    /* [NDI] */
    const void*  users = d_in[8];                /* [NQ] int32 or int64 */
    const void*  items = d_in[9];
    float* out = (float*)d_out;

    float *A, *light, *intra, *invs, *l2w, *l1w;
    int *l2s, *l2d, *l1s, *l1d, *ini, *needA, *remap, *cnt;
    uint8_t* needL;
    cudaGetSymbolAddress((void**)&A, g_A);
    cudaGetSymbolAddress((void**)&light, g_light);
    cudaGetSymbolAddress((void**)&intra, g_intra);
    cudaGetSymbolAddress((void**)&invs, g_invs);
    cudaGetSymbolAddress((void**)&l2s, g_l2s);
    cudaGetSymbolAddress((void**)&l2d, g_l2d);
    cudaGetSymbolAddress((void**)&l2w, g_l2w);
    cudaGetSymbolAddress((void**)&l1s, g_l1s);
    cudaGetSymbolAddress((void**)&l1d, g_l1d);
    cudaGetSymbolAddress((void**)&l1w, g_l1w);
    cudaGetSymbolAddress((void**)&ini, g_ini);
    cudaGetSymbolAddress((void**)&needA, g_needA);
    cudaGetSymbolAddress((void**)&remap, g_remap);
    cudaGetSymbolAddress((void**)&needL, g_needL);
    cudaGetSymbolAddress((void**)&cnt, g_cnt);

    const size_t nd8 = (size_t)NDOM * 8;
    const size_t nu8 = (size_t)NDU * 8;
    const unsigned EG = gb((size_t)NE * 8);      /* worst-case scatter grid */
    const unsigned IG = gb((size_t)NALL * 8);    /* worst-case initA grid */

    /* --- setup: flags, masks, remap, degrees --- */
    k_preset<<<1, 256>>>(cnt);
    k_detect<<<64, 256>>>((const int*)users, (const int*)items);
    k_zero_b<<<gb(NDOM), 256>>>(needL, NDOM);
    k_fill_m1<<<gb(NALL), 256>>>(remap, NALL);
    k_zero_i<<<gb((size_t)4 * NALL), 256>>>(needA, (size_t)4 * NALL);
    k_zero_f<<<gb((size_t)4 * NALL), 256>>>(invs, (size_t)4 * NALL);
    k_needL<<<gb(NQ), 256>>>(needL, users, items);
    k_remapG<<<gb(NDOM), 256>>>(remap, needL, uid, iid);
    k_deg_all<<<gb((size_t)4 * NE), 256>>>(dom, sep, invs);
    k_rsqrt_all<<<gb((size_t)4 * NALL), 256>>>(invs, (size_t)4 * NALL);

    /* --- compaction --- */
    k_passA<<<gb((size_t)4 * NE), 256>>>(dom, sep, invs, needL, remap, needA,
                                         cnt, l2s, l2d, l2w, ini);
    k_passB<<<gb((size_t)4 * NE), 256>>>(dom, sep, invs, needA, cnt, l1s, l1d, l1w);

    /* --- output accumulator inits --- */
    k_init_split<<<gb(nd8), 256>>>((float4*)intra, (const float4*)domu,
                                   (const float4*)domi, nu8, nd8);
    k_light_init<<<gb(nd8), 256>>>((float4*)light, (const float4*)aggru,
                                   (const float4*)aggri, uid, iid);

    /* --- 4 convs: initA -> L1 scatter -> L2 scatter --- */
    for (int set = 0; set < 4; set++) {
        const float* xu = (set == 0) ? domu : aggru;
        const float* xi = (set == 0) ? domi : aggri;
        int split = (set == 0) ? NDU : NTU;
        float* tgt = (set == 0) ? intra : light;
        size_t off = (size_t)set * NE;
        k_initA<<<IG, 256>>>(ini + (size_t)set * NALL, &cnt[(8 + set) * CPAD],
                             xu, xi, split, A);
        k_scatL1<<<EG, 256>>>(l1s + off, l1d + off, l1w + off, &cnt[(4 + set) * CPAD],
                              xu, xi, split, A);
        k_scatL2<<<EG, 256>>>(l2s + off, l2d + off, l2w + off, &cnt[set * CPAD],
                              A, tgt);
    }

    /* --- final pairwise dots --- */
    k_gamma<<<NQ / 8, 256>>>(users, items, light, intra, out);
}

// round 7
// speedup vs baseline: 9.1303x; 1.5646x over previous
#include <cuda_runtime.h>
#include <stdint.h>

#define NDU 60000
#define NDI 90000
#define NDOM (NDU + NDI)      /* 150000 */
#define NTU 200000
#define NTI 300000
#define NALL (NTU + NTI)      /* 500000 */
#define NE  2000000
#define DIM 32
#define NQ  8192
#define ALPHA 0.1f
#define BETA  0.9f
#define CPAD 256              /* counter stride (1KB) -> distinct L2 slices */
#define NBITW ((4 * NALL + 31) / 32)

/* ---------------- static device scratch (no allocs allowed) ---------------- */
__device__ __align__(16) float g_A[(size_t)4 * NALL * DIM];   /* 256 MB, per-set h1 */
__device__ __align__(16) float g_res[(size_t)2 * NDOM * DIM]; /* intra | light */
__device__ float    g_invs[4 * (size_t)NALL];
__device__ int      g_l1s[4 * (size_t)NE];   /* packed: table<<30 | src row */
__device__ int      g_l1d[4 * (size_t)NE];   /* global A row */
__device__ float    g_l1w[4 * (size_t)NE];
__device__ int      g_l2s[4 * (size_t)NE];   /* global A row */
__device__ int      g_l2d[4 * (size_t)NE];   /* original dst node (for weight) */
__device__ int      g_l2r[4 * (size_t)NE];   /* result row */
__device__ float    g_l2w[4 * (size_t)NE];
__device__ int      g_ini[4 * (size_t)NALL]; /* global A rows to initialize */
__device__ unsigned g_needA[NBITW];          /* bitmask */
__device__ int      g_remap[NALL];
__device__ uint8_t  g_needL[NDOM];
__device__ int      g_cnt[3 * CPAD];         /* 0:L2  CPAD:L1  2*CPAD:ini */
__device__ int      g_f[2];

/* ---------------- edge-list addressing ---------------- */
__device__ __forceinline__ const int* src_ptr(int set, const int* dom, const int* sep) {
    return (set == 0) ? dom : sep + (size_t)(set - 1) * 2 * NE;
}
__device__ __forceinline__ const int* dst_ptr(int set, const int* dom, const int* sep) {
    return (set == 0) ? dom + NE : sep + (size_t)(set - 1) * 2 * NE + NE;
}

/* warp-aggregated append (counter uniform per warp) */
__device__ __forceinline__ int wagg_append(int* ctr, bool pred) {
    unsigned m = __ballot_sync(0xffffffffu, pred);
    if (!m) return -1;
    int lane = threadIdx.x & 31;
    int leader = __ffs(m) - 1;
    int base = 0;
    if (lane == leader) base = atomicAdd(ctr, __popc(m));
    base = __shfl_sync(0xffffffffu, base, leader);
    return pred ? base + __popc(m & ((1u << lane) - 1u)) : -1;
}

/* ---------------- setup ---------------- */
__global__ void k_preset(int* cnt) {
    for (int i = threadIdx.x; i < 3 * CPAD; i += blockDim.x) cnt[i] = 0;
    if (threadIdx.x < 2) g_f[threadIdx.x] = 1;
}
__global__ void k_detect(const int* __restrict__ a, const int* __restrict__ b) {
    int arr = blockIdx.x >> 5;
    const int* p = arr ? b : a;
    int i = (blockIdx.x & 31) * 256 + threadIdx.x;
    if (i < NQ && p[2 * i + 1] != 0) g_f[arr] = 0;
}
/* one combined clear: invs, needA bits, remap, needL */
__global__ void k_clear(float* __restrict__ invs, unsigned* __restrict__ needA,
                        int* __restrict__ remap, uint8_t* __restrict__ needL) {
    size_t i = (size_t)blockIdx.x * blockDim.x + threadIdx.x;
    if (i < (size_t)4 * NALL) invs[i] = 0.f;
    if (i < NBITW) needA[i] = 0u;
    if (i < NALL) remap[i] = -1;
    if (i < NDOM) needL[i] = 0;
}
__global__ void k_needL(uint8_t* __restrict__ needL, const void* __restrict__ users,
                        const void* __restrict__ items) {
    int i = blockIdx.x * blockDim.x + threadIdx.x;
    if (i >= NQ) return;
    long long u  = g_f[0] ? ((const long long*)users)[i] : (long long)((const int*)users)[i];
    long long it = g_f[1] ? ((const long long*)items)[i] : (long long)((const int*)items)[i];
    needL[u] = 1;
    needL[NDU + it] = 1;
}
__global__ void k_remapG(int* __restrict__ remap, const uint8_t* __restrict__ needL,
                         const int* __restrict__ uid, const int* __restrict__ iid) {
    int r = blockIdx.x * blockDim.x + threadIdx.x;
    if (r >= NDOM || !needL[r]) return;
    int node = (r < NDU) ? uid[r] : NTU + iid[r - NDU];
    remap[node] = r;
}

/* ---------------- fused degree histogram + layer-2 compaction ------------ */
/* exact grid: 4*NE threads; set uniform per warp (NE % 32 == 0) */
__global__ void k_degA(const int* __restrict__ dom, const int* __restrict__ sep,
                       float* __restrict__ invs, const uint8_t* __restrict__ needL,
                       const int* __restrict__ remap, unsigned* __restrict__ needA,
                       int* __restrict__ cnt, int* __restrict__ l2s, int* __restrict__ l2d,
                       int* __restrict__ l2r, int* __restrict__ ini) {
    size_t t = (size_t)blockIdx.x * blockDim.x + threadIdx.x;
    int set = (int)(t / NE);
    int e   = (int)(t - (size_t)set * NE);
    int s = __ldg(src_ptr(set, dom, sep) + e);
    int d = __ldg(dst_ptr(set, dom, sep) + e);
    atomicAdd(&invs[(size_t)set * NALL + d], 1.0f);
    bool valid;
    int rrow;
    if (set == 0) { valid = (__ldg(needL + d) != 0); rrow = d; }
    else          { int m = __ldg(remap + d); valid = (m >= 0); rrow = NDOM + m; }
    int pos = wagg_append(&cnt[0], valid);
    if (valid) {
        l2s[pos] = set * NALL + s;
        l2d[pos] = d;
        l2r[pos] = rrow;
    }
    bool fresh = false;
    if (valid) {
        int idx = set * NALL + s;
        unsigned old = atomicOr(&needA[idx >> 5], 1u << (idx & 31));
        fresh = !(old & (1u << (idx & 31)));
    }
    int ipos = wagg_append(&cnt[2 * CPAD], fresh);
    if (fresh) ini[ipos] = set * NALL + s;
}
__global__ void k_rsqrt_all(float* d, size_t n) {
    size_t i = (size_t)blockIdx.x * blockDim.x + threadIdx.x;
    if (i < n) d[i] = rsqrtf(fmaxf(d[i], 1.0f));
}
/* layer-1 compaction (after rsqrt; weights inline). exact grid. */
__global__ void k_passB(const int* __restrict__ dom, const int* __restrict__ sep,
                        const float* __restrict__ invs, const unsigned* __restrict__ needA,
                        int* __restrict__ cnt, int* __restrict__ l1s, int* __restrict__ l1d,
                        float* __restrict__ l1w) {
    size_t t = (size_t)blockIdx.x * blockDim.x + threadIdx.x;
    int set = (int)(t / NE);
    int e   = (int)(t - (size_t)set * NE);
    int s = __ldg(src_ptr(set, dom, sep) + e);
    int d = __ldg(dst_ptr(set, dom, sep) + e);
    int idx = set * NALL + d;
    bool valid = (__ldg(needA + (idx >> 5)) >> (idx & 31)) & 1u;
    int pos = wagg_append(&cnt[CPAD], valid);
    if (valid) {
        const float* iv = invs + (size_t)set * NALL;
        l1s[pos] = s | ((set > 0) << 30);
        l1d[pos] = idx;
        l1w[pos] = BETA * __ldg(iv + s) * __ldg(iv + d);
    }
}
/* post-compute layer-2 weights over compacted list */
__global__ void k_wL2(const int* __restrict__ l2s, const int* __restrict__ l2d,
                      float* __restrict__ l2w, const float* __restrict__ invs,
                      const int* __restrict__ cnt) {
    int n = __ldg(&cnt[0]);
    int stride = gridDim.x * blockDim.x;
    for (int i = blockIdx.x * blockDim.x + threadIdx.x; i < n; i += stride) {
        int srow = __ldg(l2s + i);
        int set = srow / NALL;
        int so = srow - set * NALL;
        l2w[i] = BETA * __ldg(invs + srow) * __ldg(invs + (size_t)set * NALL + __ldg(l2d + i));
        (void)so;
    }
}

/* ---------------- gathers from split input tables ---------------- */
__device__ __forceinline__ float4 gatherX(const float* __restrict__ xu,
                                          const float* __restrict__ xi,
                                          int splitU, int node, int lane) {
    const float* p = (node < splitU) ? xu + (size_t)node * DIM
                                     : xi + (size_t)(node - splitU) * DIM;
    return *(const float4*)(p + lane * 4);
}

/* ---------------- result init: intra = ALPHA*x_dom, light = 3*ALPHA*x_agg -- */
__global__ void k_init_res(float4* __restrict__ res,
                           const float* __restrict__ du, const float* __restrict__ di,
                           const float* __restrict__ au, const float* __restrict__ ai,
                           const int* __restrict__ uid, const int* __restrict__ iid) {
    size_t i = (size_t)blockIdx.x * blockDim.x + threadIdx.x;
    const size_t nd8 = (size_t)NDOM * 8;
    if (i >= 2 * nd8) return;
    if (i < nd8) {
        int r = (int)(i >> 3), c = (int)(i & 7);
        float4 v = gatherX(du, di, NDU, r, c);
        res[i] = make_float4(ALPHA * v.x, ALPHA * v.y, ALPHA * v.z, ALPHA * v.w);
    } else {
        size_t j = i - nd8;
        int r = (int)(j >> 3), c = (int)(j & 7);
        int node = (r < NDU) ? __ldg(uid + r) : NTU + __ldg(iid + r - NDU);
        float4 v = gatherX(au, ai, NTU, node, c);
        float k = 3.0f * ALPHA;
        res[i] = make_float4(k * v.x, k * v.y, k * v.z, k * v.w);
    }
}

/* ---------------- grid-stride list kernels, 8 lanes per item ------------- */
__global__ void k_initA(const int* __restrict__ ini, const int* __restrict__ cnt,
                        const float* __restrict__ du, const float* __restrict__ di,
                        const float* __restrict__ au, const float* __restrict__ ai,
                        float* __restrict__ A) {
    size_t work = (size_t)__ldg(&cnt[2 * CPAD]) * 8;
    size_t stride = (size_t)gridDim.x * blockDim.x;
    for (size_t t = (size_t)blockIdx.x * blockDim.x + threadIdx.x; t < work; t += stride) {
        int r = (int)(t >> 3), lane = (int)(t & 7);
        int arow = __ldg(ini + r);
        int set = arow / NALL;
        int so = arow - set * NALL;
        float4 v = (set == 0) ? gatherX(du, di, NDU, so, lane)
                              : gatherX(au, ai, NTU, so, lane);
        *(float4*)(A + (size_t)arow * DIM + lane * 4) =
            make_float4(ALPHA * v.x, ALPHA * v.y, ALPHA * v.z, ALPHA * v.w);
    }
}
__global__ void k_scatL1(const int* __restrict__ l1s, const int* __restrict__ l1d,
                         const float* __restrict__ l1w, const int* __restrict__ cnt,
                         const float* __restrict__ du, const float* __restrict__ di,
                         const float* __restrict__ au, const float* __restrict__ ai,
                         float* __restrict__ A) {
    size_t work = (size_t)__ldg(&cnt[CPAD]) * 8;
    size_t stride = (size_t)gridDim.x * blockDim.x;
    for (size_t t = (size_t)blockIdx.x * blockDim.x + threadIdx.x; t < work; t += stride) {
        int e = (int)(t >> 3), lane = (int)(t & 7);
        int code = __ldg(l1s + e);
        int drow = __ldg(l1d + e);
        float w = __ldg(l1w + e);
        int so = code & 0x3FFFFFFF;
        float4 v = (code >> 30) ? gatherX(au, ai, NTU, so, lane)
                                : gatherX(du, di, NDU, so, lane);
        float* o = A + (size_t)drow * DIM + lane * 4;
        asm volatile("red.global.add.v4.f32 [%0], {%1,%2,%3,%4};"
                     :: "l"(o), "f"(v.x * w), "f"(v.y * w),
                        "f"(v.z * w), "f"(v.w * w) : "memory");
    }
}
__global__ void k_scatL2(const int* __restrict__ l2s, const int* __restrict__ l2r,
                         const float* __restrict__ l2w, const int* __restrict__ cnt,
                         const float* __restrict__ A, float* __restrict__ res) {
    size_t work = (size_t)__ldg(&cnt[0]) * 8;
    size_t stride = (size_t)gridDim.x * blockDim.x;
    for (size_t t = (size_t)blockIdx.x * blockDim.x + threadIdx.x; t < work; t += stride) {
        int e = (int)(t >> 3), lane = (int)(t & 7);
        int srow = __ldg(l2s + e);
        int rrow = __ldg(l2r + e);
        float w = __ldg(l2w + e);
        float4 v = *(const float4*)(A + (size_t)srow * DIM + lane * 4);
        float* o = res + (size_t)rrow * DIM + lane * 4;
        asm volatile("red.global.add.v4.f32 [%0], {%1,%2,%3,%4};"
                     :: "l"(o), "f"(v.x * w), "f"(v.y * w),
                        "f"(v.z * w), "f"(v.w * w) : "memory");
    }
}

/* gamma[p] = dot(light_u, light_i)/9 + dot(intra_u, intra_i); one warp/pair */
__global__ void k_gamma(const void* __restrict__ users, const void* __restrict__ items,
                        const float* __restrict__ res, float* __restrict__ out) {
    int p = (blockIdx.x * blockDim.x + threadIdx.x) >> 5;
    int lane = threadIdx.x & 31;
    if (p >= NQ) return;
    long long u  = g_f[0] ? ((const long long*)users)[p] : (long long)((const int*)users)[p];
    long long it = g_f[1] ? ((const long long*)items)[p] : (long long)((const int*)items)[p];
    size_t ui = (size_t)u * DIM + lane;                       /* intra user */
    size_t ii = ((size_t)NDU + it) * DIM + lane;              /* intra item */
    size_t ul = ((size_t)NDOM + u) * DIM + lane;              /* light user */
    size_t il = ((size_t)NDOM + NDU + it) * DIM + lane;       /* light item */
    float v = res[ul] * res[il] * (1.0f / 9.0f) + res[ui] * res[ii];
#pragma unroll
    for (int o = 16; o; o >>= 1) v += __shfl_xor_sync(0xffffffffu, v, o);
    if (lane == 0) out[p] = v;
}

/* ---------------- host side ---------------- */
static inline unsigned gb(size_t n) { return (unsigned)((n + 255) / 256); }

extern "C" void kernel_launch(void* const* d_in, const int* in_sizes, int n_in,
                              void* d_out, int out_size) {
    const int*   dom   = (const int*)d_in[0];
    const int*   sep   = (const int*)d_in[1];
    const float* aggru = (const float*)d_in[2];
    const float* aggri = (const float*)d_in[3];
    const float* domu  = (const float*)d_in[4];
    const float* domi  = (const float*)d_in[5];
    const int*   uid   = (const int*)d_in[6];
    const int*   iid   = (const int*)d_in[7];
    const void*  users = d_in[8];
    const void*  items = d_in[9];
    float* out = (float*)d_out;

    float *A, *res, *invs, *l1w, *l2w;
    int *l1s, *l1d, *l2s, *l2d, *l2r, *ini, *remap, *cnt;
    unsigned* needA;
    uint8_t* needL;
    cudaGetSymbolAddress((void**)&A, g_A);
    cudaGetSymbolAddress((void**)&res, g_res);
    cudaGetSymbolAddress((void**)&invs, g_invs);
    cudaGetSymbolAddress((void**)&l1s, g_l1s);
    cudaGetSymbolAddress((void**)&l1d, g_l1d);
    cudaGetSymbolAddress((void**)&l1w, g_l1w);
    cudaGetSymbolAddress((void**)&l2s, g_l2s);
    cudaGetSymbolAddress((void**)&l2d, g_l2d);
    cudaGetSymbolAddress((void**)&l2r, g_l2r);
    cudaGetSymbolAddress((void**)&l2w, g_l2w);
    cudaGetSymbolAddress((void**)&ini, g_ini);
    cudaGetSymbolAddress((void**)&needA, g_needA);
    cudaGetSymbolAddress((void**)&remap, g_remap);
    cudaGetSymbolAddress((void**)&needL, g_needL);
    cudaGetSymbolAddress((void**)&cnt, g_cnt);

    /* setup */
    k_preset<<<1, 256>>>(cnt);
    k_detect<<<64, 256>>>((const int*)users, (const int*)items);
    k_clear<<<gb((size_t)4 * NALL), 256>>>(invs, needA, remap, needL);
    k_needL<<<gb(NQ), 256>>>(needL, users, items);
    k_remapG<<<gb(NDOM), 256>>>(remap, needL, uid, iid);

    /* fused degree + layer-2 compaction; then rsqrt, layer-1 compaction, L2 weights */
    k_degA<<<(unsigned)((size_t)4 * NE / 256), 256>>>(dom, sep, invs, needL, remap,
                                                      needA, cnt, l2s, l2d, l2r, ini);
    k_rsqrt_all<<<gb((size_t)4 * NALL), 256>>>(invs, (size_t)4 * NALL);
    k_passB<<<(unsigned)((size_t)4 * NE / 256), 256>>>(dom, sep, invs, needA,
                                                       cnt, l1s, l1d, l1w);
    k_wL2<<<512, 256>>>(l2s, l2d, l2w, invs, cnt);

    /* inits */
    k_init_res<<<gb((size_t)2 * NDOM * 8), 256>>>((float4*)res, domu, domi,
                                                  aggru, aggri, uid, iid);
    k_initA<<<1024, 256>>>(ini, cnt, domu, domi, aggru, aggri, A);

    /* fused scatters across all 4 convs */
    k_scatL1<<<2048, 256>>>(l1s, l1d, l1w, cnt, domu, domi, aggru, aggri, A);
    k_scatL2<<<2048, 256>>>(l2s, l2r, l2w, cnt, A, res);

    /* final dots */
    k_gamma<<<NQ / 8, 256>>>(users, items, res, out);
}

// round 8
// speedup vs baseline: 9.1698x; 1.0043x over previous
#include <cuda_runtime.h>
#include <stdint.h>

#define NDU 60000
#define NDI 90000
#define NDOM (NDU + NDI)      /* 150000 */
#define NTU 200000
#define NTI 300000
#define NALL (NTU + NTI)      /* 500000 */
#define NE  2000000
#define DIM 32
#define NQ  8192
#define ALPHA 0.1f
#define BETA  0.9f
#define CPAD 256              /* counter stride (1KB) -> distinct L2 slices */
#define NBITW ((4 * NALL + 31) / 32)

/* ---------------- static device scratch (no allocs allowed) ---------------- */
__device__ __align__(16) float g_A[(size_t)4 * NALL * DIM];   /* dense prefix used */
__device__ __align__(16) float g_res[(size_t)2 * NDOM * DIM]; /* intra | light */
__device__ float    g_deg[4 * (size_t)NALL];  /* raw degrees */
__device__ int      g_l1s[4 * (size_t)NE];    /* packed: table<<30 | src node */
__device__ int      g_l1d[4 * (size_t)NE];    /* dense A row */
__device__ float    g_l1w[4 * (size_t)NE];
__device__ int      g_l2s[4 * (size_t)NE];    /* global node -> dense A row */
__device__ int      g_l2d[4 * (size_t)NE];    /* dst node (for weight) */
__device__ int      g_l2r[4 * (size_t)NE];    /* result row */
__device__ float    g_l2w[4 * (size_t)NE];
__device__ int      g_ini[4 * (size_t)NALL];  /* dense row -> global node */
__device__ int      g_aid[4 * (size_t)NALL];  /* global node -> dense row */
__device__ unsigned g_needA[NBITW];
__device__ int      g_remap[NALL];
__device__ uint8_t  g_needL[NDOM];
__device__ int      g_cnt[3 * CPAD];          /* 0:L2  CPAD:L1  2*CPAD:ini */
__device__ int      g_f[2];

/* ---------------- edge-list addressing ---------------- */
__device__ __forceinline__ const int* src_ptr(int set, const int* dom, const int* sep) {
    return (set == 0) ? dom : sep + (size_t)(set - 1) * 2 * NE;
}
__device__ __forceinline__ const int* dst_ptr(int set, const int* dom, const int* sep) {
    return (set == 0) ? dom + NE : sep + (size_t)(set - 1) * 2 * NE + NE;
}

/* warp-aggregated append (counter uniform per warp) */
__device__ __forceinline__ int wagg_append(int* ctr, bool pred) {
    unsigned m = __ballot_sync(0xffffffffu, pred);
    if (!m) return -1;
    int lane = threadIdx.x & 31;
    int leader = __ffs(m) - 1;
    int base = 0;
    if (lane == leader) base = atomicAdd(ctr, __popc(m));
    base = __shfl_sync(0xffffffffu, base, leader);
    return pred ? base + __popc(m & ((1u << lane) - 1u)) : -1;
}

__device__ __forceinline__ float nrm(float deg) { return rsqrtf(fmaxf(deg, 1.0f)); }

/* ---------------- setup ---------------- */
__global__ void k_preset(int* cnt) {
    for (int i = threadIdx.x; i < 3 * CPAD; i += blockDim.x) cnt[i] = 0;
    if (threadIdx.x < 2) g_f[threadIdx.x] = 1;
}
__global__ void k_detect(const int* __restrict__ a, const int* __restrict__ b) {
    int arr = blockIdx.x >> 5;
    const int* p = arr ? b : a;
    int i = (blockIdx.x & 31) * 256 + threadIdx.x;
    if (i < NQ && p[2 * i + 1] != 0) g_f[arr] = 0;
}
/* one combined clear: deg, aid, needA bits, remap, needL */
__global__ void k_clear(float* __restrict__ deg, int* __restrict__ aid,
                        unsigned* __restrict__ needA, int* __restrict__ remap,
                        uint8_t* __restrict__ needL) {
    size_t i = (size_t)blockIdx.x * blockDim.x + threadIdx.x;
    if (i < (size_t)4 * NALL) { deg[i] = 0.f; aid[i] = -1; }
    if (i < NBITW) needA[i] = 0u;
    if (i < NALL) remap[i] = -1;
    if (i < NDOM) needL[i] = 0;
}
/* fused: mark needed dom rows AND build global-node remap from queries */
__global__ void k_needmap(uint8_t* __restrict__ needL, int* __restrict__ remap,
                          const int* __restrict__ uid, const int* __restrict__ iid,
                          const void* __restrict__ users, const void* __restrict__ items) {
    int i = blockIdx.x * blockDim.x + threadIdx.x;
    if (i >= NQ) return;
    long long u  = g_f[0] ? ((const long long*)users)[i] : (long long)((const int*)users)[i];
    long long it = g_f[1] ? ((const long long*)items)[i] : (long long)((const int*)items)[i];
    needL[u] = 1;
    needL[NDU + it] = 1;
    remap[__ldg(uid + u)] = (int)u;
    remap[NTU + __ldg(iid + it)] = NDU + (int)it;
}

/* ---------------- fused degree histogram + layer-2 compaction ------------ */
/* exact grid: 4*NE threads; set uniform per warp (NE % 32 == 0) */
__global__ void k_degA(const int* __restrict__ dom, const int* __restrict__ sep,
                       float* __restrict__ deg, const uint8_t* __restrict__ needL,
                       const int* __restrict__ remap, unsigned* __restrict__ needA,
                       int* __restrict__ aid, int* __restrict__ cnt,
                       int* __restrict__ l2s, int* __restrict__ l2d,
                       int* __restrict__ l2r, int* __restrict__ ini) {
    size_t t = (size_t)blockIdx.x * blockDim.x + threadIdx.x;
    int set = (int)(t / NE);
    int e   = (int)(t - (size_t)set * NE);
    int s = __ldg(src_ptr(set, dom, sep) + e);
    int d = __ldg(dst_ptr(set, dom, sep) + e);
    atomicAdd(&deg[(size_t)set * NALL + d], 1.0f);
    bool valid;
    int rrow;
    if (set == 0) { valid = (__ldg(needL + d) != 0); rrow = d; }
    else          { int m = __ldg(remap + d); valid = (m >= 0); rrow = NDOM + m; }
    int pos = wagg_append(&cnt[0], valid);
    if (valid) {
        l2s[pos] = set * NALL + s;
        l2d[pos] = d;
        l2r[pos] = rrow;
    }
    bool fresh = false;
    int idx = set * NALL + s;
    if (valid) {
        unsigned old = atomicOr(&needA[idx >> 5], 1u << (idx & 31));
        fresh = !(old & (1u << (idx & 31)));
    }
    int ipos = wagg_append(&cnt[2 * CPAD], fresh);
    if (fresh) { ini[ipos] = idx; aid[idx] = ipos; }
}

/* layer-1 compaction: filter by needA, resolve dense dst row, weight inline */
__global__ void k_passB(const int* __restrict__ dom, const int* __restrict__ sep,
                        const float* __restrict__ deg, const unsigned* __restrict__ needA,
                        const int* __restrict__ aid, int* __restrict__ cnt,
                        int* __restrict__ l1s, int* __restrict__ l1d,
                        float* __restrict__ l1w) {
    size_t t = (size_t)blockIdx.x * blockDim.x + threadIdx.x;
    int set = (int)(t / NE);
    int e   = (int)(t - (size_t)set * NE);
    int s = __ldg(src_ptr(set, dom, sep) + e);
    int d = __ldg(dst_ptr(set, dom, sep) + e);
    int idx = set * NALL + d;
    bool valid = (__ldg(needA + (idx >> 5)) >> (idx & 31)) & 1u;
    int pos = wagg_append(&cnt[CPAD], valid);
    if (valid) {
        const float* dg = deg + (size_t)set * NALL;
        l1s[pos] = s | ((set > 0) << 30);
        l1d[pos] = __ldg(aid + idx);
        l1w[pos] = BETA * nrm(__ldg(dg + s)) * nrm(__ldg(dg + d));
    }
}
/* resolve layer-2: weight + src node -> dense A row (grid-stride, ~390K) */
__global__ void k_resL2(int* __restrict__ l2s, const int* __restrict__ l2d,
                        float* __restrict__ l2w, const float* __restrict__ deg,
                        const int* __restrict__ aid, const int* __restrict__ cnt) {
    int n = __ldg(&cnt[0]);
    int stride = gridDim.x * blockDim.x;
    for (int i = blockIdx.x * blockDim.x + threadIdx.x; i < n; i += stride) {
        int srow = l2s[i];
        int set = srow / NALL;
        l2w[i] = BETA * nrm(__ldg(deg + srow)) *
                 nrm(__ldg(deg + (size_t)set * NALL + __ldg(l2d + i)));
        l2s[i] = __ldg(aid + srow);
    }
}

/* ---------------- gathers from split input tables ---------------- */
__device__ __forceinline__ float4 gatherX(const float* __restrict__ xu,
                                          const float* __restrict__ xi,
                                          int splitU, int node, int lane) {
    const float* p = (node < splitU) ? xu + (size_t)node * DIM
                                     : xi + (size_t)(node - splitU) * DIM;
    return *(const float4*)(p + lane * 4);
}

/* ---------------- result init: intra = ALPHA*x_dom, light = 3*ALPHA*x_agg -- */
__global__ void k_init_res(float4* __restrict__ res,
                           const float* __restrict__ du, const float* __restrict__ di,
                           const float* __restrict__ au, const float* __restrict__ ai,
                           const int* __restrict__ uid, const int* __restrict__ iid) {
    size_t i = (size_t)blockIdx.x * blockDim.x + threadIdx.x;
    const size_t nd8 = (size_t)NDOM * 8;
    if (i >= 2 * nd8) return;
    if (i < nd8) {
        int r = (int)(i >> 3), c = (int)(i & 7);
        float4 v = gatherX(du, di, NDU, r, c);
        res[i] = make_float4(ALPHA * v.x, ALPHA * v.y, ALPHA * v.z, ALPHA * v.w);
    } else {
        size_t j = i - nd8;
        int r = (int)(j >> 3), c = (int)(j & 7);
        int node = (r < NDU) ? __ldg(uid + r) : NTU + __ldg(iid + r - NDU);
        float4 v = gatherX(au, ai, NTU, node, c);
        float k = 3.0f * ALPHA;
        res[i] = make_float4(k * v.x, k * v.y, k * v.z, k * v.w);
    }
}

/* ---------------- grid-stride list kernels, 8 lanes per item ------------- */
__global__ void k_initA(const int* __restrict__ ini, const int* __restrict__ cnt,
                        const float* __restrict__ du, const float* __restrict__ di,
                        const float* __restrict__ au, const float* __restrict__ ai,
                        float* __restrict__ A) {
    size_t work = (size_t)__ldg(&cnt[2 * CPAD]) * 8;
    size_t stride = (size_t)gridDim.x * blockDim.x;
    for (size_t t = (size_t)blockIdx.x * blockDim.x + threadIdx.x; t < work; t += stride) {
        int r = (int)(t >> 3), lane = (int)(t & 7);
        int node = __ldg(ini + r);                 /* dense row r holds this node */
        int set = node / NALL;
        int so = node - set * NALL;
        float4 v = (set == 0) ? gatherX(du, di, NDU, so, lane)
                              : gatherX(au, ai, NTU, so, lane);
        *(float4*)(A + (size_t)r * DIM + lane * 4) =
            make_float4(ALPHA * v.x, ALPHA * v.y, ALPHA * v.z, ALPHA * v.w);
    }
}
__global__ void k_scatL1(const int* __restrict__ l1s, const int* __restrict__ l1d,
                         const float* __restrict__ l1w, const int* __restrict__ cnt,
                         const float* __restrict__ du, const float* __restrict__ di,
                         const float* __restrict__ au, const float* __restrict__ ai,
                         float* __restrict__ A) {
    size_t work = (size_t)__ldg(&cnt[CPAD]) * 8;
    size_t stride = (size_t)gridDim.x * blockDim.x;
    for (size_t t = (size_t)blockIdx.x * blockDim.x + threadIdx.x; t < work; t += stride) {
        int e = (int)(t >> 3), lane = (int)(t & 7);
        int code = __ldg(l1s + e);
        int drow = __ldg(l1d + e);                 /* dense */
        float w = __ldg(l1w + e);
        int so = code & 0x3FFFFFFF;
        float4 v = (code >> 30) ? gatherX(au, ai, NTU, so, lane)
                                : gatherX(du, di, NDU, so, lane);
        float* o = A + (size_t)drow * DIM + lane * 4;
        asm volatile("red.global.add.v4.f32 [%0], {%1,%2,%3,%4};"
                     :: "l"(o), "f"(v.x * w), "f"(v.y * w),
                        "f"(v.z * w), "f"(v.w * w) : "memory");
    }
}
__global__ void k_scatL2(const int* __restrict__ l2s, const int* __restrict__ l2r,
                         const float* __restrict__ l2w, const int* __restrict__ cnt,
                         const float* __restrict__ A, float* __restrict__ res) {
    size_t work = (size_t)__ldg(&cnt[0]) * 8;
    size_t stride = (size_t)gridDim.x * blockDim.x;
    for (size_t t = (size_t)blockIdx.x * blockDim.x + threadIdx.x; t < work; t += stride) {
        int e = (int)(t >> 3), lane = (int)(t & 7);
        int srow = __ldg(l2s + e);                 /* dense */
        int rrow = __ldg(l2r + e);
        float w = __ldg(l2w + e);
        float4 v = *(const float4*)(A + (size_t)srow * DIM + lane * 4);
        float* o = res + (size_t)rrow * DIM + lane * 4;
        asm volatile("red.global.add.v4.f32 [%0], {%1,%2,%3,%4};"
                     :: "l"(o), "f"(v.x * w), "f"(v.y * w),
                        "f"(v.z * w), "f"(v.w * w) : "memory");
    }
}

/* gamma[p] = dot(light_u, light_i)/9 + dot(intra_u, intra_i); one warp/pair */
__global__ void k_gamma(const void* __restrict__ users, const void* __restrict__ items,
                        const float* __restrict__ res, float* __restrict__ out) {
    int p = (blockIdx.x * blockDim.x + threadIdx.x) >> 5;
    int lane = threadIdx.x & 31;
    if (p >= NQ) return;
    long long u  = g_f[0] ? ((const long long*)users)[p] : (long long)((const int*)users)[p];
    long long it = g_f[1] ? ((const long long*)items)[p] : (long long)((const int*)items)[p];
    size_t ui = (size_t)u * DIM + lane;
    size_t ii = ((size_t)NDU + it) * DIM + lane;
    size_t ul = ((size_t)NDOM + u) * DIM + lane;
    size_t il = ((size_t)NDOM + NDU + it) * DIM + lane;
    float v = res[ul] * res[il] * (1.0f / 9.0f) + res[ui] * res[ii];
#pragma unroll
    for (int o = 16; o; o >>= 1) v += __shfl_xor_sync(0xffffffffu, v, o);
    if (lane == 0) out[p] = v;
}

/* ---------------- host side ---------------- */
static inline unsigned gb(size_t n) { return (unsigned)((n + 255) / 256); }

extern "C" void kernel_launch(void* const* d_in, const int* in_sizes, int n_in,
                              void* d_out, int out_size) {
    const int*   dom   = (const int*)d_in[0];
    const int*   sep   = (const int*)d_in[1];
    const float* aggru = (const float*)d_in[2];
    const float* aggri = (const float*)d_in[3];
    const float* domu  = (const float*)d_in[4];
    const float* domi  = (const float*)d_in[5];
    const int*   uid   = (const int*)d_in[6];
    const int*   iid   = (const int*)d_in[7];
    const void*  users = d_in[8];
    const void*  items = d_in[9];
    float* out = (float*)d_out;

    float *A, *res, *deg, *l1w, *l2w;
    int *l1s, *l1d, *l2s, *l2d, *l2r, *ini, *aid, *remap, *cnt;
    unsigned* needA;
    uint8_t* needL;
    cudaGetSymbolAddress((void**)&A, g_A);
    cudaGetSymbolAddress((void**)&res, g_res);
    cudaGetSymbolAddress((void**)&deg, g_deg);
    cudaGetSymbolAddress((void**)&l1s, g_l1s);
    cudaGetSymbolAddress((void**)&l1d, g_l1d);
    cudaGetSymbolAddress((void**)&l1w, g_l1w);
    cudaGetSymbolAddress((void**)&l2s, g_l2s);
    cudaGetSymbolAddress((void**)&l2d, g_l2d);
    cudaGetSymbolAddress((void**)&l2r, g_l2r);
    cudaGetSymbolAddress((void**)&l2w, g_l2w);
    cudaGetSymbolAddress((void**)&ini, g_ini);
    cudaGetSymbolAddress((void**)&aid, g_aid);
    cudaGetSymbolAddress((void**)&needA, g_needA);
    cudaGetSymbolAddress((void**)&remap, g_remap);
    cudaGetSymbolAddress((void**)&needL, g_needL);
    cudaGetSymbolAddress((void**)&cnt, g_cnt);

    /* setup */
    k_preset<<<1, 256>>>(cnt);
    k_detect<<<64, 256>>>((const int*)users, (const int*)items);
    k_clear<<<gb((size_t)4 * NALL), 256>>>(deg, aid, needA, remap, needL);
    k_needmap<<<gb(NQ), 256>>>(needL, remap, uid, iid, users, items);

    /* compaction: fused degree + layer-2; then layer-1 + L2 resolve */
    k_degA<<<(unsigned)((size_t)4 * NE / 256), 256>>>(dom, sep, deg, needL, remap,
                                                      needA, aid, cnt, l2s, l2d, l2r, ini);
    k_passB<<<(unsigned)((size_t)4 * NE / 256), 256>>>(dom, sep, deg, needA, aid,
                                                       cnt, l1s, l1d, l1w);
    k_resL2<<<512, 256>>>(l2s, l2d, l2w, deg, aid, cnt);

    /* inits */
    k_init_res<<<gb((size_t)2 * NDOM * 8), 256>>>((float4*)res, domu, domi,
                                                  aggru, aggri, uid, iid);
    k_initA<<<1024, 256>>>(ini, cnt, domu, domi, aggru, aggri, A);

    /* fused scatters across all 4 convs */
    k_scatL1<<<2048, 256>>>(l1s, l1d, l1w, cnt, domu, domi, aggru, aggri, A);
    k_scatL2<<<1024, 256>>>(l2s, l2r, l2w, cnt, A, res);

    /* final dots */
    k_gamma<<<NQ / 8, 256>>>(users, items, res, out);
}

// round 9
// speedup vs baseline: 12.5356x; 1.3670x over previous
#include <cuda_runtime.h>
#include <stdint.h>

#define NDU 60000
#define NDI 90000
#define NDOM (NDU + NDI)      /* 150000 */
#define NTU 200000
#define NTI 300000
#define NALL (NTU + NTI)      /* 500000 */
#define NE  2000000
#define DIM 32
#define NQ  8192
#define ALPHA 0.1f
#define BETA  0.9f
#define CPAD 256              /* counter stride (1KB) -> distinct L2 slices */
#define NBITW ((4 * NALL) / 32)   /* 62500 exact */

/* ---------------- static device scratch (no allocs allowed) ---------------- */
__device__ __align__(16) float g_A[(size_t)4 * NALL * DIM];   /* dense prefix used */
__device__ __align__(16) float g_res[(size_t)2 * NDOM * DIM]; /* intra | light */
__device__ __align__(16) float    g_deg[4 * (size_t)NALL];
__device__ __align__(16) int      g_l2s[4 * (size_t)NE];   /* global node -> dense A row */
__device__ __align__(16) int      g_l2d[4 * (size_t)NE];   /* dst node (for weight) */
__device__ __align__(16) int      g_l2r[4 * (size_t)NE];   /* result row */
__device__ __align__(16) float    g_l2w[4 * (size_t)NE];
__device__ __align__(16) int      g_ini[4 * (size_t)NALL]; /* dense row -> global node */
__device__ __align__(16) int      g_aid[4 * (size_t)NALL]; /* global node -> dense row */
__device__ __align__(16) unsigned g_needA[NBITW];
__device__ __align__(16) int      g_remap[NALL];
__device__ __align__(16) uint8_t  g_needL[NDOM];
__device__ int      g_cnt[3 * CPAD];          /* 0:L2  2*CPAD:ini */
__device__ int      g_f[2] = {1, 1};          /* monotone: detect only writes 0 */

/* ---------------- edge-list addressing ---------------- */
__device__ __forceinline__ const int* src_ptr(int set, const int* dom, const int* sep) {
    return (set == 0) ? dom : sep + (size_t)(set - 1) * 2 * NE;
}
__device__ __forceinline__ const int* dst_ptr(int set, const int* dom, const int* sep) {
    return (set == 0) ? dom + NE : sep + (size_t)(set - 1) * 2 * NE + NE;
}

/* warp-aggregated append (counter uniform per warp) */
__device__ __forceinline__ int wagg_append(int* ctr, bool pred) {
    unsigned m = __ballot_sync(0xffffffffu, pred);
    if (!m) return -1;
    int lane = threadIdx.x & 31;
    int leader = __ffs(m) - 1;
    int base = 0;
    if (lane == leader) base = atomicAdd(ctr, __popc(m));
    base = __shfl_sync(0xffffffffu, base, leader);
    return pred ? base + __popc(m & ((1u << lane) - 1u)) : -1;
}

__device__ __forceinline__ float nrm(float deg) { return rsqrtf(fmaxf(deg, 1.0f)); }

/* ---------------- setup ---------------- */
/* idempotent width detect: writes 0 only; g_f statically {1,1}; int32 data
   always re-flips to 0 on every call, int64 stays 1 -> deterministic */
__global__ void k_detect(const int* __restrict__ a, const int* __restrict__ b) {
    int arr = blockIdx.x >> 5;
    const int* p = arr ? b : a;
    int i = (blockIdx.x & 31) * 256 + threadIdx.x;
    if (i < NQ && p[2 * i + 1] != 0) g_f[arr] = 0;
}
/* one vectorized clear: deg, remap, needL, needA, counters */
__global__ void k_clear(float4* __restrict__ deg4, int4* __restrict__ remap4,
                        uint4* __restrict__ needL4, uint4* __restrict__ needA4,
                        int* __restrict__ cnt) {
    int i = blockIdx.x * blockDim.x + threadIdx.x;
    if (i < 500000) deg4[i] = make_float4(0.f, 0.f, 0.f, 0.f);           /* 4*NALL floats */
    if (i < 125000) remap4[i] = make_int4(-1, -1, -1, -1);               /* NALL ints */
    if (i < 9375)   needL4[i] = make_uint4(0u, 0u, 0u, 0u);              /* NDOM bytes */
    if (i < 15625)  needA4[i] = make_uint4(0u, 0u, 0u, 0u);              /* NBITW words */
    if (i < 3 * CPAD) cnt[i] = 0;
}
/* fused: mark needed dom rows AND build global-node remap from queries */
__global__ void k_needmap(uint8_t* __restrict__ needL, int* __restrict__ remap,
                          const int* __restrict__ uid, const int* __restrict__ iid,
                          const void* __restrict__ users, const void* __restrict__ items) {
    int i = blockIdx.x * blockDim.x + threadIdx.x;
    if (i >= NQ) return;
    long long u  = g_f[0] ? ((const long long*)users)[i] : (long long)((const int*)users)[i];
    long long it = g_f[1] ? ((const long long*)items)[i] : (long long)((const int*)items)[i];
    needL[u] = 1;
    needL[NDU + it] = 1;
    remap[__ldg(uid + u)] = (int)u;
    remap[NTU + __ldg(iid + it)] = NDU + (int)it;
}

/* ---------------- fused degree histogram + layer-2 compaction ------------ */
__global__ void k_degA(const int* __restrict__ dom, const int* __restrict__ sep,
                       float* __restrict__ deg, const uint8_t* __restrict__ needL,
                       const int* __restrict__ remap, unsigned* __restrict__ needA,
                       int* __restrict__ aid, int* __restrict__ cnt,
                       int* __restrict__ l2s, int* __restrict__ l2d,
                       int* __restrict__ l2r, int* __restrict__ ini) {
    size_t t = (size_t)blockIdx.x * blockDim.x + threadIdx.x;
    int set = (int)(t / NE);
    int e   = (int)(t - (size_t)set * NE);
    int s = __ldg(src_ptr(set, dom, sep) + e);
    int d = __ldg(dst_ptr(set, dom, sep) + e);
    atomicAdd(&deg[(size_t)set * NALL + d], 1.0f);
    bool valid;
    int rrow;
    if (set == 0) { valid = (__ldg(needL + d) != 0); rrow = d; }
    else          { int m = __ldg(remap + d); valid = (m >= 0); rrow = NDOM + m; }
    int pos = wagg_append(&cnt[0], valid);
    if (valid) {
        l2s[pos] = set * NALL + s;
        l2d[pos] = d;
        l2r[pos] = rrow;
    }
    bool fresh = false;
    int idx = set * NALL + s;
    if (valid) {
        unsigned old = atomicOr(&needA[idx >> 5], 1u << (idx & 31));
        fresh = !(old & (1u << (idx & 31)));
    }
    int ipos = wagg_append(&cnt[2 * CPAD], fresh);
    if (fresh) { ini[ipos] = idx; aid[idx] = ipos; }
}

/* resolve layer-2: weight + src node -> dense A row (grid-stride, ~390K) */
__global__ void k_resL2(int* __restrict__ l2s, const int* __restrict__ l2d,
                        float* __restrict__ l2w, const float* __restrict__ deg,
                        const int* __restrict__ aid, const int* __restrict__ cnt) {
    int n = __ldg(&cnt[0]);
    int stride = gridDim.x * blockDim.x;
    for (int i = blockIdx.x * blockDim.x + threadIdx.x; i < n; i += stride) {
        int srow = l2s[i];
        int set = srow / NALL;
        l2w[i] = BETA * nrm(__ldg(deg + srow)) *
                 nrm(__ldg(deg + (size_t)set * NALL + __ldg(l2d + i)));
        l2s[i] = __ldg(aid + srow);
    }
}

/* ---------------- gathers from split input tables ---------------- */
__device__ __forceinline__ float4 gatherX(const float* __restrict__ xu,
                                          const float* __restrict__ xi,
                                          int splitU, int node, int lane) {
    const float* p = (node < splitU) ? xu + (size_t)node * DIM
                                     : xi + (size_t)(node - splitU) * DIM;
    return *(const float4*)(p + lane * 4);
}

/* ---------------- result init: intra = ALPHA*x_dom, light = 3*ALPHA*x_agg -- */
__global__ void k_init_res(float4* __restrict__ res,
                           const float* __restrict__ du, const float* __restrict__ di,
                           const float* __restrict__ au, const float* __restrict__ ai,
                           const int* __restrict__ uid, const int* __restrict__ iid) {
    size_t i = (size_t)blockIdx.x * blockDim.x + threadIdx.x;
    const size_t nd8 = (size_t)NDOM * 8;
    if (i >= 2 * nd8) return;
    if (i < nd8) {
        int r = (int)(i >> 3), c = (int)(i & 7);
        float4 v = gatherX(du, di, NDU, r, c);
        res[i] = make_float4(ALPHA * v.x, ALPHA * v.y, ALPHA * v.z, ALPHA * v.w);
    } else {
        size_t j = i - nd8;
        int r = (int)(j >> 3), c = (int)(j & 7);
        int node = (r < NDU) ? __ldg(uid + r) : NTU + __ldg(iid + r - NDU);
        float4 v = gatherX(au, ai, NTU, node, c);
        float k = 3.0f * ALPHA;
        res[i] = make_float4(k * v.x, k * v.y, k * v.z, k * v.w);
    }
}

/* ---------------- initA: A[dense r] = ALPHA * x[node(r)] ---------------- */
__global__ void k_initA(const int* __restrict__ ini, const int* __restrict__ cnt,
                        const float* __restrict__ du, const float* __restrict__ di,
                        const float* __restrict__ au, const float* __restrict__ ai,
                        float* __restrict__ A) {
    size_t work = (size_t)__ldg(&cnt[2 * CPAD]) * 8;
    size_t stride = (size_t)gridDim.x * blockDim.x;
    for (size_t t = (size_t)blockIdx.x * blockDim.x + threadIdx.x; t < work; t += stride) {
        int r = (int)(t >> 3), lane = (int)(t & 7);
        int node = __ldg(ini + r);
        int set = node / NALL;
        int so = node - set * NALL;
        float4 v = (set == 0) ? gatherX(du, di, NDU, so, lane)
                              : gatherX(au, ai, NTU, so, lane);
        *(float4*)(A + (size_t)r * DIM + lane * 4) =
            make_float4(ALPHA * v.x, ALPHA * v.y, ALPHA * v.z, ALPHA * v.w);
    }
}

/* ---------------- fused layer-1: filter raw edges + warp-compacted scatter -
   32 edges per warp; survivors (~27%) processed 4 at a time x 8 lanes.     */
__global__ void k_scatL1f(const int* __restrict__ dom, const int* __restrict__ sep,
                          const float* __restrict__ deg, const unsigned* __restrict__ needA,
                          const int* __restrict__ aid,
                          const float* __restrict__ du, const float* __restrict__ di,
                          const float* __restrict__ au, const float* __restrict__ ai,
                          float* __restrict__ A) {
    const unsigned total = 4u * NE;
    unsigned lane = threadIdx.x & 31;
    unsigned warpStride = (gridDim.x * blockDim.x) >> 5;
    unsigned warpId = ((blockIdx.x * blockDim.x) >> 5) + (threadIdx.x >> 5);
    for (unsigned base = warpId * 32; base < total; base += warpStride * 32) {
        unsigned t = base + lane;
        int set = (int)(t / NE);                 /* uniform per warp: NE%32==0 */
        int e   = (int)(t - (unsigned)set * NE);
        int s = __ldg(src_ptr(set, dom, sep) + e);
        int d = __ldg(dst_ptr(set, dom, sep) + e);
        int idx = set * NALL + d;
        bool valid = (__ldg(needA + (idx >> 5)) >> (idx & 31)) & 1u;
        float w = 0.f;
        int drow = 0, scode = 0;
        if (valid) {
            w = BETA * nrm(__ldg(deg + (size_t)set * NALL + s)) * nrm(__ldg(deg + idx));
            drow = __ldg(aid + idx);
            scode = s | ((set > 0) << 30);
        }
        unsigned m = __ballot_sync(0xffffffffu, valid);
        int nv = __popc(m);
        for (int k = 0; k < nv; k += 4) {
            int j = k + (int)(lane >> 3);
            unsigned sl = __fns(m, 0, j + 1);    /* lane owning j-th survivor */
            int   sc = __shfl_sync(0xffffffffu, scode, sl & 31);
            int   dr = __shfl_sync(0xffffffffu, drow,  sl & 31);
            float ww = __shfl_sync(0xffffffffu, w,     sl & 31);
            if (j < nv) {
                int so = sc & 0x3FFFFFFF;
                int sub = (int)(lane & 7);
                float4 v = (sc >> 30) ? gatherX(au, ai, NTU, so, sub)
                                      : gatherX(du, di, NDU, so, sub);
                float* o = A + (size_t)dr * DIM + sub * 4;
                asm volatile("red.global.add.v4.f32 [%0], {%1,%2,%3,%4};"
                             :: "l"(o), "f"(v.x * ww), "f"(v.y * ww),
                                "f"(v.z * ww), "f"(v.w * ww) : "memory");
            }
        }
    }
}

/* ---------------- layer-2 scatter over compacted list ---------------- */
__global__ void k_scatL2(const int* __restrict__ l2s, const int* __restrict__ l2r,
                         const float* __restrict__ l2w, const int* __restrict__ cnt,
                         const float* __restrict__ A, float* __restrict__ res) {
    size_t work = (size_t)__ldg(&cnt[0]) * 8;
    size_t stride = (size_t)gridDim.x * blockDim.x;
    for (size_t t = (size_t)blockIdx.x * blockDim.x + threadIdx.x; t < work; t += stride) {
        int e = (int)(t >> 3), lane = (int)(t & 7);
        int srow = __ldg(l2s + e);               /* dense */
        int rrow = __ldg(l2r + e);
        float w = __ldg(l2w + e);
        float4 v = *(const float4*)(A + (size_t)srow * DIM + lane * 4);
        float* o = res + (size_t)rrow * DIM + lane * 4;
        asm volatile("red.global.add.v4.f32 [%0], {%1,%2,%3,%4};"
                     :: "l"(o), "f"(v.x * w), "f"(v.y * w),
                        "f"(v.z * w), "f"(v.w * w) : "memory");
    }
}

/* gamma[p] = dot(light_u, light_i)/9 + dot(intra_u, intra_i); one warp/pair */
__global__ void k_gamma(const void* __restrict__ users, const void* __restrict__ items,
                        const float* __restrict__ res, float* __restrict__ out) {
    int p = (blockIdx.x * blockDim.x + threadIdx.x) >> 5;
    int lane = threadIdx.x & 31;
    if (p >= NQ) return;
    long long u  = g_f[0] ? ((const long long*)users)[p] : (long long)((const int*)users)[p];
    long long it = g_f[1] ? ((const long long*)items)[p] : (long long)((const int*)items)[p];
    size_t ui = (size_t)u * DIM + lane;
    size_t ii = ((size_t)NDU + it) * DIM + lane;
    size_t ul = ((size_t)NDOM + u) * DIM + lane;
    size_t il = ((size_t)NDOM + NDU + it) * DIM + lane;
    float v = res[ul] * res[il] * (1.0f / 9.0f) + res[ui] * res[ii];
#pragma unroll
    for (int o = 16; o; o >>= 1) v += __shfl_xor_sync(0xffffffffu, v, o);
    if (lane == 0) out[p] = v;
}

/* ---------------- host side ---------------- */
static inline unsigned gb(size_t n) { return (unsigned)((n + 255) / 256); }

extern "C" void kernel_launch(void* const* d_in, const int* in_sizes, int n_in,
                              void* d_out, int out_size) {
    const int*   dom   = (const int*)d_in[0];
    const int*   sep   = (const int*)d_in[1];
    const float* aggru = (const float*)d_in[2];
    const float* aggri = (const float*)d_in[3];
    const float* domu  = (const float*)d_in[4];
    const float* domi  = (const float*)d_in[5];
    const int*   uid   = (const int*)d_in[6];
    const int*   iid   = (const int*)d_in[7];
    const void*  users = d_in[8];
    const void*  items = d_in[9];
    float* out = (float*)d_out;

    float *A, *res, *deg, *l2w;
    int *l2s, *l2d, *l2r, *ini, *aid, *remap, *cnt;
    unsigned* needA;
    uint8_t* needL;
    cudaGetSymbolAddress((void**)&A, g_A);
    cudaGetSymbolAddress((void**)&res, g_res);
    cudaGetSymbolAddress((void**)&deg, g_deg);
    cudaGetSymbolAddress((void**)&l2s, g_l2s);
    cudaGetSymbolAddress((void**)&l2d, g_l2d);
    cudaGetSymbolAddress((void**)&l2r, g_l2r);
    cudaGetSymbolAddress((void**)&l2w, g_l2w);
    cudaGetSymbolAddress((void**)&ini, g_ini);
    cudaGetSymbolAddress((void**)&aid, g_aid);
    cudaGetSymbolAddress((void**)&needA, g_needA);
    cudaGetSymbolAddress((void**)&remap, g_remap);
    cudaGetSymbolAddress((void**)&needL, g_needL);
    cudaGetSymbolAddress((void**)&cnt, g_cnt);

    /* setup */
    k_detect<<<64, 256>>>((const int*)users, (const int*)items);
    k_clear<<<gb(500000), 256>>>((float4*)deg, (int4*)remap, (uint4*)needL,
                                 (uint4*)needA, cnt);
    k_needmap<<<gb(NQ), 256>>>(needL, remap, uid, iid, users, items);

    /* fused degree + layer-2 compaction */
    k_degA<<<(unsigned)((size_t)4 * NE / 256), 256>>>(dom, sep, deg, needL, remap,
                                                      needA, aid, cnt, l2s, l2d, l2r, ini);

    /* inits + layer-1 fused scatter */
    k_initA<<<1024, 256>>>(ini, cnt, domu, domi, aggru, aggri, A);
    k_scatL1f<<<2048, 256>>>(dom, sep, deg, needA, aid,
                             domu, domi, aggru, aggri, A);

    /* layer-2 resolve + result init + scatter */
    k_resL2<<<512, 256>>>(l2s, l2d, l2w, deg, aid, cnt);
    k_init_res<<<gb((size_t)2 * NDOM * 8), 256>>>((float4*)res, domu, domi,
                                                  aggru, aggri, uid, iid);
    k_scatL2<<<1024, 256>>>(l2s, l2r, l2w, cnt, A, res);

    /* final dots */
    k_gamma<<<NQ / 8, 256>>>(users, items, res, out);
}

// round 10
// speedup vs baseline: 16.1680x; 1.2898x over previous
#include <cuda_runtime.h>
#include <stdint.h>

#define NDU 60000
#define NDI 90000
#define NDOM (NDU + NDI)      /* 150000 */
#define NTU 200000
#define NTI 300000
#define NALL (NTU + NTI)      /* 500000 */
#define NE  2000000
#define DIM 32
#define NQ  8192
#define ALPHA 0.1f
#define BETA  0.9f
#define CPAD 256              /* counter stride (1KB) -> distinct L2 slices */
#define NBITW ((4 * NALL) / 32)   /* 62500 exact */
#define DBLK 512              /* k_degA block size (16 warps) */

/* ---------------- static device scratch (no allocs allowed) ---------------- */
__device__ __align__(16) float g_A[(size_t)4 * NALL * DIM];   /* dense prefix used */
__device__ __align__(16) float g_res[(size_t)2 * NDOM * DIM]; /* intra | light */
__device__ __align__(16) float    g_deg[4 * (size_t)NALL];
__device__ __align__(16) int      g_l2s[4 * (size_t)NE];   /* global node -> dense A row */
__device__ __align__(16) int      g_l2d[4 * (size_t)NE];   /* dst node (for weight) */
__device__ __align__(16) int      g_l2r[4 * (size_t)NE];   /* result row */
__device__ __align__(16) float    g_l2w[4 * (size_t)NE];
__device__ __align__(16) int      g_ini[4 * (size_t)NALL]; /* dense row -> global node */
__device__ __align__(16) int      g_aid[4 * (size_t)NALL]; /* global node -> dense row */
__device__ __align__(16) unsigned g_needA[NBITW];
__device__ __align__(16) int      g_remap[NALL];
__device__ __align__(16) uint8_t  g_needL[NDOM];
__device__ int      g_cnt[3 * CPAD];          /* 0:L2  2*CPAD:ini */
__device__ int      g_f[2] = {1, 1};          /* monotone: detect only writes 0 */

/* ---------------- edge-list addressing ---------------- */
__device__ __forceinline__ const int* src_ptr(int set, const int* dom, const int* sep) {
    return (set == 0) ? dom : sep + (size_t)(set - 1) * 2 * NE;
}
__device__ __forceinline__ const int* dst_ptr(int set, const int* dom, const int* sep) {
    return (set == 0) ? dom + NE : sep + (size_t)(set - 1) * 2 * NE + NE;
}

__device__ __forceinline__ float nrm(float deg) { return rsqrtf(fmaxf(deg, 1.0f)); }

/* ---------------- setup ---------------- */
/* idempotent width detect: writes 0 only; g_f statically {1,1} */
__global__ void k_detect(const int* __restrict__ a, const int* __restrict__ b) {
    int arr = blockIdx.x >> 5;
    const int* p = arr ? b : a;
    int i = (blockIdx.x & 31) * 256 + threadIdx.x;
    if (i < NQ && p[2 * i + 1] != 0) g_f[arr] = 0;
}
/* one vectorized clear: deg, remap, needL, needA, counters */
__global__ void k_clear(float4* __restrict__ deg4, int4* __restrict__ remap4,
                        uint4* __restrict__ needL4, uint4* __restrict__ needA4,
                        int* __restrict__ cnt) {
    int i = blockIdx.x * blockDim.x + threadIdx.x;
    if (i < 500000) deg4[i] = make_float4(0.f, 0.f, 0.f, 0.f);           /* 4*NALL floats */
    if (i < 125000) remap4[i] = make_int4(-1, -1, -1, -1);               /* NALL ints */
    if (i < 9375)   needL4[i] = make_uint4(0u, 0u, 0u, 0u);              /* NDOM bytes */
    if (i < 15625)  needA4[i] = make_uint4(0u, 0u, 0u, 0u);              /* NBITW words */
    if (i < 3 * CPAD) cnt[i] = 0;
}
/* fused: mark needed dom rows AND build global-node remap from queries */
__global__ void k_needmap(uint8_t* __restrict__ needL, int* __restrict__ remap,
                          const int* __restrict__ uid, const int* __restrict__ iid,
                          const void* __restrict__ users, const void* __restrict__ items) {
    int i = blockIdx.x * blockDim.x + threadIdx.x;
    if (i >= NQ) return;
    long long u  = g_f[0] ? ((const long long*)users)[i] : (long long)((const int*)users)[i];
    long long it = g_f[1] ? ((const long long*)items)[i] : (long long)((const int*)items)[i];
    needL[u] = 1;
    needL[NDU + it] = 1;
    remap[__ldg(uid + u)] = (int)u;
    remap[NTU + __ldg(iid + it)] = NDU + (int)it;
}

/* ---------------- fused degree histogram + layer-2 compaction ------------
   Block-aggregated appends: ONE atomicAdd per block per counter.          */
__global__ __launch_bounds__(DBLK) void
k_degA(const int* __restrict__ dom, const int* __restrict__ sep,
       float* __restrict__ deg, const uint8_t* __restrict__ needL,
       const int* __restrict__ remap, unsigned* __restrict__ needA,
       int* __restrict__ aid, int* __restrict__ cnt,
       int* __restrict__ l2s, int* __restrict__ l2d,
       int* __restrict__ l2r, int* __restrict__ ini) {
    __shared__ int w2[DBLK / 32], wi[DBLK / 32];
    __shared__ int base2, basei;
    size_t t = (size_t)blockIdx.x * DBLK + threadIdx.x;
    int lane = threadIdx.x & 31, wid = threadIdx.x >> 5;
    int set = (int)(t / NE);
    int e   = (int)(t - (size_t)set * NE);
    int s = __ldg(src_ptr(set, dom, sep) + e);
    int d = __ldg(dst_ptr(set, dom, sep) + e);
    atomicAdd(&deg[(size_t)set * NALL + d], 1.0f);
    bool valid;
    int rrow;
    if (set == 0) { valid = (__ldg(needL + d) != 0); rrow = d; }
    else          { int m = __ldg(remap + d); valid = (m >= 0); rrow = NDOM + m; }
    bool fresh = false;
    int idx = set * NALL + s;
    if (valid) {
        unsigned old = atomicOr(&needA[idx >> 5], 1u << (idx & 31));
        fresh = !(old & (1u << (idx & 31)));
    }
    unsigned m2 = __ballot_sync(0xffffffffu, valid);
    unsigned mi = __ballot_sync(0xffffffffu, fresh);
    if (lane == 0) { w2[wid] = __popc(m2); wi[wid] = __popc(mi); }
    __syncthreads();
    if (threadIdx.x == 0) {
        int tot = 0;
#pragma unroll
        for (int i = 0; i < DBLK / 32; i++) { int c = w2[i]; w2[i] = tot; tot += c; }
        base2 = tot ? atomicAdd(&cnt[0], tot) : 0;
    } else if (threadIdx.x == 32) {
        int tot = 0;
#pragma unroll
        for (int i = 0; i < DBLK / 32; i++) { int c = wi[i]; wi[i] = tot; tot += c; }
        basei = tot ? atomicAdd(&cnt[2 * CPAD], tot) : 0;
    }
    __syncthreads();
    unsigned ltm = (1u << lane) - 1u;
    if (valid) {
        int pos = base2 + w2[wid] + __popc(m2 & ltm);
        l2s[pos] = idx;
        l2d[pos] = d;
        l2r[pos] = rrow;
    }
    if (fresh) {
        int ipos = basei + wi[wid] + __popc(mi & ltm);
        ini[ipos] = idx;
        aid[idx] = ipos;
    }
}

/* resolve layer-2: weight + src node -> dense A row (grid-stride, ~390K) */
__global__ void k_resL2(int* __restrict__ l2s, const int* __restrict__ l2d,
                        float* __restrict__ l2w, const float* __restrict__ deg,
                        const int* __restrict__ aid, const int* __restrict__ cnt) {
    int n = __ldg(&cnt[0]);
    int stride = gridDim.x * blockDim.x;
    for (int i = blockIdx.x * blockDim.x + threadIdx.x; i < n; i += stride) {
        int srow = l2s[i];
        int set = srow / NALL;
        l2w[i] = BETA * nrm(__ldg(deg + srow)) *
                 nrm(__ldg(deg + (size_t)set * NALL + __ldg(l2d + i)));
        l2s[i] = __ldg(aid + srow);
    }
}

/* ---------------- gathers from split input tables ---------------- */
__device__ __forceinline__ float4 gatherX(const float* __restrict__ xu,
                                          const float* __restrict__ xi,
                                          int splitU, int node, int lane) {
    const float* p = (node < splitU) ? xu + (size_t)node * DIM
                                     : xi + (size_t)(node - splitU) * DIM;
    return *(const float4*)(p + lane * 4);
}

/* ---------------- result init: intra = ALPHA*x_dom, light = 3*ALPHA*x_agg -- */
__global__ void k_init_res(float4* __restrict__ res,
                           const float* __restrict__ du, const float* __restrict__ di,
                           const float* __restrict__ au, const float* __restrict__ ai,
                           const int* __restrict__ uid, const int* __restrict__ iid) {
    size_t i = (size_t)blockIdx.x * blockDim.x + threadIdx.x;
    const size_t nd8 = (size_t)NDOM * 8;
    if (i >= 2 * nd8) return;
    if (i < nd8) {
        int r = (int)(i >> 3), c = (int)(i & 7);
        float4 v = gatherX(du, di, NDU, r, c);
        res[i] = make_float4(ALPHA * v.x, ALPHA * v.y, ALPHA * v.z, ALPHA * v.w);
    } else {
        size_t j = i - nd8;
        int r = (int)(j >> 3), c = (int)(j & 7);
        int node = (r < NDU) ? __ldg(uid + r) : NTU + __ldg(iid + r - NDU);
        float4 v = gatherX(au, ai, NTU, node, c);
        float k = 3.0f * ALPHA;
        res[i] = make_float4(k * v.x, k * v.y, k * v.z, k * v.w);
    }
}

/* ---------------- initA: A[dense r] = ALPHA * x[node(r)] ---------------- */
__global__ void k_initA(const int* __restrict__ ini, const int* __restrict__ cnt,
                        const float* __restrict__ du, const float* __restrict__ di,
                        const float* __restrict__ au, const float* __restrict__ ai,
                        float* __restrict__ A) {
    size_t work = (size_t)__ldg(&cnt[2 * CPAD]) * 8;
    size_t stride = (size_t)gridDim.x * blockDim.x;
    for (size_t t = (size_t)blockIdx.x * blockDim.x + threadIdx.x; t < work; t += stride) {
        int r = (int)(t >> 3), lane = (int)(t & 7);
        int node = __ldg(ini + r);
        int set = node / NALL;
        int so = node - set * NALL;
        float4 v = (set == 0) ? gatherX(du, di, NDU, so, lane)
                              : gatherX(au, ai, NTU, so, lane);
        *(float4*)(A + (size_t)r * DIM + lane * 4) =
            make_float4(ALPHA * v.x, ALPHA * v.y, ALPHA * v.z, ALPHA * v.w);
    }
}

/* ---------------- fused layer-1: filter raw edges + warp-compacted scatter -
   32 edges per warp; survivors (~27%) processed 4 at a time x 8 lanes.     */
__global__ void k_scatL1f(const int* __restrict__ dom, const int* __restrict__ sep,
                          const float* __restrict__ deg, const unsigned* __restrict__ needA,
                          const int* __restrict__ aid,
                          const float* __restrict__ du, const float* __restrict__ di,
                          const float* __restrict__ au, const float* __restrict__ ai,
                          float* __restrict__ A) {
    const unsigned total = 4u * NE;
    unsigned lane = threadIdx.x & 31;
    unsigned warpStride = (gridDim.x * blockDim.x) >> 5;
    unsigned warpId = ((blockIdx.x * blockDim.x) >> 5) + (threadIdx.x >> 5);
    for (unsigned base = warpId * 32; base < total; base += warpStride * 32) {
        unsigned t = base + lane;
        int set = (int)(t / NE);                 /* uniform per warp: NE%32==0 */
        int e   = (int)(t - (unsigned)set * NE);
        int s = __ldg(src_ptr(set, dom, sep) + e);
        int d = __ldg(dst_ptr(set, dom, sep) + e);
        int idx = set * NALL + d;
        bool valid = (__ldg(needA + (idx >> 5)) >> (idx & 31)) & 1u;
        float w = 0.f;
        int drow = 0, scode = 0;
        if (valid) {
            w = BETA * nrm(__ldg(deg + (size_t)set * NALL + s)) * nrm(__ldg(deg + idx));
            drow = __ldg(aid + idx);
            scode = s | ((set > 0) << 30);
        }
        unsigned m = __ballot_sync(0xffffffffu, valid);
        int nv = __popc(m);
        for (int k = 0; k < nv; k += 4) {
            int j = k + (int)(lane >> 3);
            unsigned sl = __fns(m, 0, j + 1);
            int   sc = __shfl_sync(0xffffffffu, scode, sl & 31);
            int   dr = __shfl_sync(0xffffffffu, drow,  sl & 31);
            float ww = __shfl_sync(0xffffffffu, w,     sl & 31);
            if (j < nv) {
                int so = sc & 0x3FFFFFFF;
                int sub = (int)(lane & 7);
                float4 v = (sc >> 30) ? gatherX(au, ai, NTU, so, sub)
                                      : gatherX(du, di, NDU, so, sub);
                float* o = A + (size_t)dr * DIM + sub * 4;
                asm volatile("red.global.add.v4.f32 [%0], {%1,%2,%3,%4};"
                             :: "l"(o), "f"(v.x * ww), "f"(v.y * ww),
                                "f"(v.z * ww), "f"(v.w * ww) : "memory");
            }
        }
    }
}

/* ---------------- layer-2 scatter over compacted list ---------------- */
__global__ void k_scatL2(const int* __restrict__ l2s, const int* __restrict__ l2r,
                         const float* __restrict__ l2w, const int* __restrict__ cnt,
                         const float* __restrict__ A, float* __restrict__ res) {
    size_t work = (size_t)__ldg(&cnt[0]) * 8;
    size_t stride = (size_t)gridDim.x * blockDim.x;
    for (size_t t = (size_t)blockIdx.x * blockDim.x + threadIdx.x; t < work; t += stride) {
        int e = (int)(t >> 3), lane = (int)(t & 7);
        int srow = __ldg(l2s + e);
        int rrow = __ldg(l2r + e);
        float w = __ldg(l2w + e);
        float4 v = *(const float4*)(A + (size_t)srow * DIM + lane * 4);
        float* o = res + (size_t)rrow * DIM + lane * 4;
        asm volatile("red.global.add.v4.f32 [%0], {%1,%2,%3,%4};"
                     :: "l"(o), "f"(v.x * w), "f"(v.y * w),
                        "f"(v.z * w), "f"(v.w * w) : "memory");
    }
}

/* gamma[p] = dot(light_u, light_i)/9 + dot(intra_u, intra_i); one warp/pair */
__global__ void k_gamma(const void* __restrict__ users, const void* __restrict__ items,
                        const float* __restrict__ res, float* __restrict__ out) {
    int p = (blockIdx.x * blockDim.x + threadIdx.x) >> 5;
    int lane = threadIdx.x & 31;
    if (p >= NQ) return;
    long long u  = g_f[0] ? ((const long long*)users)[p] : (long long)((const int*)users)[p];
    long long it = g_f[1] ? ((const long long*)items)[p] : (long long)((const int*)items)[p];
    size_t ui = (size_t)u * DIM + lane;
    size_t ii = ((size_t)NDU + it) * DIM + lane;
    size_t ul = ((size_t)NDOM + u) * DIM + lane;
    size_t il = ((size_t)NDOM + NDU + it) * DIM + lane;
    float v = res[ul] * res[il] * (1.0f / 9.0f) + res[ui] * res[ii];
#pragma unroll
    for (int o = 16; o; o >>= 1) v += __shfl_xor_sync(0xffffffffu, v, o);
    if (lane == 0) out[p] = v;
}

/* ---------------- host side ---------------- */
static inline unsigned gb(size_t n) { return (unsigned)((n + 255) / 256); }

extern "C" void kernel_launch(void* const* d_in, const int* in_sizes, int n_in,
                              void* d_out, int out_size) {
    const int*   dom   = (const int*)d_in[0];
    const int*   sep   = (const int*)d_in[1];
    const float* aggru = (const float*)d_in[2];
    const float* aggri = (const float*)d_in[3];
    const float* domu  = (const float*)d_in[4];
    const float* domi  = (const float*)d_in[5];
    const int*   uid   = (const int*)d_in[6];
    const int*   iid   = (const int*)d_in[7];
    const void*  users = d_in[8];
    const void*  items = d_in[9];
    float* out = (float*)d_out;

    float *A, *res, *deg, *l2w;
    int *l2s, *l2d, *l2r, *ini, *aid, *remap, *cnt;
    unsigned* needA;
    uint8_t* needL;
    cudaGetSymbolAddress((void**)&A, g_A);
    cudaGetSymbolAddress((void**)&res, g_res);
    cudaGetSymbolAddress((void**)&deg, g_deg);
    cudaGetSymbolAddress((void**)&l2s, g_l2s);
    cudaGetSymbolAddress((void**)&l2d, g_l2d);
    cudaGetSymbolAddress((void**)&l2r, g_l2r);
    cudaGetSymbolAddress((void**)&l2w, g_l2w);
    cudaGetSymbolAddress((void**)&ini, g_ini);
    cudaGetSymbolAddress((void**)&aid, g_aid);
    cudaGetSymbolAddress((void**)&needA, g_needA);
    cudaGetSymbolAddress((void**)&remap, g_remap);
    cudaGetSymbolAddress((void**)&needL, g_needL);
    cudaGetSymbolAddress((void**)&cnt, g_cnt);

    /* setup */
    k_detect<<<64, 256>>>((const int*)users, (const int*)items);
    k_clear<<<gb(500000), 256>>>((float4*)deg, (int4*)remap, (uint4*)needL,
                                 (uint4*)needA, cnt);
    k_needmap<<<gb(NQ), 256>>>(needL, remap, uid, iid, users, items);

    /* fused degree + layer-2 compaction (block-aggregated appends) */
    k_degA<<<(unsigned)((size_t)4 * NE / DBLK), DBLK>>>(dom, sep, deg, needL, remap,
                                                        needA, aid, cnt, l2s, l2d, l2r, ini);

    /* inits + layer-1 fused scatter */
    k_initA<<<1024, 256>>>(ini, cnt, domu, domi, aggru, aggri, A);
    k_scatL1f<<<2048, 256>>>(dom, sep, deg, needA, aid,
                             domu, domi, aggru, aggri, A);

    /* layer-2 resolve + result init + scatter */
    k_resL2<<<512, 256>>>(l2s, l2d, l2w, deg, aid, cnt);
    k_init_res<<<gb((size_t)2 * NDOM * 8), 256>>>((float4*)res, domu, domi,
                                                  aggru, aggri, uid, iid);
    k_scatL2<<<1024, 256>>>(l2s, l2r, l2w, cnt, A, res);

    /* final dots */
    k_gamma<<<NQ / 8, 256>>>(users, items, res, out);
}